// round 1
// baseline (speedup 1.0000x reference)
#include <cuda_runtime.h>

// Problem constants
static constexpr int Bc   = 2;
static constexpr int Lc   = 2048;
static constexpr int Dc   = 1024;
static constexpr int Hc   = 16;
static constexpr int HDc  = 64;
static constexpr int Mc   = Bc * Lc;   // 4096 rows
static constexpr float SCALE = 0.125f; // 64^-0.5

// Scratch (allocation-free rule: __device__ globals)
__device__ float g_q[Bc * Hc * Lc * HDc];     // [B,H,L,Hd]
__device__ float g_k[Bc * Hc * Lc * HDc];
__device__ float g_v[Bc * Hc * Lc * HDc];
__device__ float g_attn[Mc * Dc];             // [B,L,D]

// ---------------------------------------------------------------------------
// QKV GEMM: C[4096,3072] = X[4096,1024] @ W^T + b, scattered into g_q/g_k/g_v
// BM=128, BN=64, BK=16, 256 threads, 8x4 micro-tile.
// ---------------------------------------------------------------------------
__global__ __launch_bounds__(256) void qkv_gemm_kernel(
    const float* __restrict__ X, const float* __restrict__ W,
    const float* __restrict__ bias) {
  __shared__ float As[16][132];
  __shared__ float Bs[16][68];
  const int tid  = threadIdx.x;
  const int tx   = tid & 15;
  const int ty   = tid >> 4;
  const int row0 = blockIdx.y * 128;
  const int col0 = blockIdx.x * 64;
  const int lr   = tid >> 2;
  const int lc   = (tid & 3) * 4;

  float acc[8][4];
#pragma unroll
  for (int i = 0; i < 8; i++)
#pragma unroll
    for (int j = 0; j < 4; j++) acc[i][j] = 0.f;

  const float* Arow0 = X + (size_t)(row0 + lr) * 1024 + lc;
  const float* Arow1 = X + (size_t)(row0 + 64 + lr) * 1024 + lc;
  const float* Brow  = W + (size_t)(col0 + lr) * 1024 + lc;

  for (int k0 = 0; k0 < 1024; k0 += 16) {
    float4 a0 = *(const float4*)(Arow0 + k0);
    float4 a1 = *(const float4*)(Arow1 + k0);
    float4 b0 = *(const float4*)(Brow + k0);
    __syncthreads();
    As[lc + 0][lr] = a0.x; As[lc + 1][lr] = a0.y;
    As[lc + 2][lr] = a0.z; As[lc + 3][lr] = a0.w;
    As[lc + 0][64 + lr] = a1.x; As[lc + 1][64 + lr] = a1.y;
    As[lc + 2][64 + lr] = a1.z; As[lc + 3][64 + lr] = a1.w;
    Bs[lc + 0][lr] = b0.x; Bs[lc + 1][lr] = b0.y;
    Bs[lc + 2][lr] = b0.z; Bs[lc + 3][lr] = b0.w;
    __syncthreads();
#pragma unroll
    for (int k = 0; k < 16; k++) {
      float4 aA = *(const float4*)&As[k][ty * 8];
      float4 aB = *(const float4*)&As[k][ty * 8 + 4];
      float4 bb = *(const float4*)&Bs[k][tx * 4];
      float am[8] = {aA.x, aA.y, aA.z, aA.w, aB.x, aB.y, aB.z, aB.w};
      float bn[4] = {bb.x, bb.y, bb.z, bb.w};
#pragma unroll
      for (int i = 0; i < 8; i++)
#pragma unroll
        for (int j = 0; j < 4; j++) acc[i][j] += am[i] * bn[j];
    }
  }

  // Epilogue: bias + scatter to q/k/v in [B,H,L,Hd]
  const int cbase = col0 + tx * 4;
  const float4 b4 = *(const float4*)(bias + cbase);
  const int three = cbase >> 10;          // 0=q 1=k 2=v (tile stays inside one)
  const int h     = (cbase & 1023) >> 6;
  const int d     = cbase & 63;
  float* dst = (three == 0) ? g_q : ((three == 1) ? g_k : g_v);
#pragma unroll
  for (int i = 0; i < 8; i++) {
    int gr = row0 + ty * 8 + i;
    int bb_ = gr >> 11;
    int l   = gr & 2047;
    float4 o = make_float4(acc[i][0] + b4.x, acc[i][1] + b4.y,
                           acc[i][2] + b4.z, acc[i][3] + b4.w);
    *(float4*)(dst + ((size_t)(bb_ * 16 + h) * 2048 + l) * 64 + d) = o;
  }
}

// ---------------------------------------------------------------------------
// Flash attention, fp32. Block = (b,h, 64-query tile). 256 threads.
// 4x4 micro-tiles for both QK^T and P·V. Online softmax, stats in registers
// (16-lane shfl reductions; each of the 16 threads of a row keeps a
// consistent copy of m / l).
// ---------------------------------------------------------------------------
__global__ __launch_bounds__(256) void attn_kernel() {
  extern __shared__ float sm[];
  float(*Qs)[68] = (float(*)[68])(sm);
  float(*Ks)[68] = (float(*)[68])(sm + 64 * 68);
  float(*Vs)[68] = (float(*)[68])(sm + 2 * 64 * 68);
  float(*Ps)[68] = (float(*)[68])(sm + 3 * 64 * 68);

  const int tid = threadIdx.x;
  const int tx  = tid & 15;   // key/dim column group
  const int ty  = tid >> 4;   // query row group
  const int q0  = blockIdx.x * 64;
  const int bh  = blockIdx.y; // b*16+h

  const float* Qg = g_q + ((size_t)bh * 2048 + q0) * 64;
  const float* Kg = g_k + (size_t)bh * 2048 * 64;
  const float* Vg = g_v + (size_t)bh * 2048 * 64;

  // Load Q tile, pre-scaled by 1/sqrt(d)
#pragma unroll
  for (int i = 0; i < 4; i++) {
    int f = tid + 256 * i;
    int r = f >> 4;
    int c = (f & 15) * 4;
    float4 qv = *(const float4*)(Qg + r * 64 + c);
    Qs[r][c + 0] = qv.x * SCALE; Qs[r][c + 1] = qv.y * SCALE;
    Qs[r][c + 2] = qv.z * SCALE; Qs[r][c + 3] = qv.w * SCALE;
  }

  float O[4][4];
  float m_old[4], l_sum[4];
#pragma unroll
  for (int i = 0; i < 4; i++) {
    m_old[i] = -1e30f;
    l_sum[i] = 0.f;
#pragma unroll
    for (int j = 0; j < 4; j++) O[i][j] = 0.f;
  }

  for (int kt = 0; kt < 32; kt++) {
    __syncthreads();  // prev iter's P·V done: safe to overwrite K/V/P
    const float* Kt = Kg + kt * 64 * 64;
    const float* Vt = Vg + kt * 64 * 64;
#pragma unroll
    for (int i = 0; i < 4; i++) {
      int f = tid + 256 * i;
      int r = f >> 4;
      int c = (f & 15) * 4;
      *(float4*)&Ks[r][c] = *(const float4*)(Kt + r * 64 + c);
      *(float4*)&Vs[r][c] = *(const float4*)(Vt + r * 64 + c);
    }
    __syncthreads();

    // S = Q K^T (4x4 per thread)
    float s[4][4];
#pragma unroll
    for (int i = 0; i < 4; i++)
#pragma unroll
      for (int j = 0; j < 4; j++) s[i][j] = 0.f;

#pragma unroll 4
    for (int d = 0; d < 64; d += 4) {
      float4 qf[4], kf[4];
#pragma unroll
      for (int i = 0; i < 4; i++) qf[i] = *(const float4*)&Qs[4 * ty + i][d];
#pragma unroll
      for (int j = 0; j < 4; j++) kf[j] = *(const float4*)&Ks[4 * tx + j][d];
#pragma unroll
      for (int i = 0; i < 4; i++)
#pragma unroll
        for (int j = 0; j < 4; j++)
          s[i][j] += qf[i].x * kf[j].x + qf[i].y * kf[j].y +
                     qf[i].z * kf[j].z + qf[i].w * kf[j].w;
    }

    // Online softmax update. Each row owned by 16 lanes (one 16-lane half).
#pragma unroll
    for (int i = 0; i < 4; i++) {
      float mx = fmaxf(fmaxf(s[i][0], s[i][1]), fmaxf(s[i][2], s[i][3]));
#pragma unroll
      for (int off = 1; off < 16; off <<= 1)
        mx = fmaxf(mx, __shfl_xor_sync(0xffffffffu, mx, off));
      float m_new = fmaxf(m_old[i], mx);
      float alpha = __expf(m_old[i] - m_new);
      float ps = 0.f;
#pragma unroll
      for (int j = 0; j < 4; j++) {
        float p = __expf(s[i][j] - m_new);
        Ps[4 * ty + i][4 * tx + j] = p;
        ps += p;
      }
#pragma unroll
      for (int off = 1; off < 16; off <<= 1)
        ps += __shfl_xor_sync(0xffffffffu, ps, off);
      l_sum[i] = l_sum[i] * alpha + ps;
      m_old[i] = m_new;
#pragma unroll
      for (int j = 0; j < 4; j++) O[i][j] *= alpha;
    }
    __syncthreads();  // P visible to all

    // O += P · V (4x4 per thread: 4 P scalars + 1 V float4 per kj)
#pragma unroll 8
    for (int kj = 0; kj < 64; kj++) {
      float4 vv = *(const float4*)&Vs[kj][4 * tx];
#pragma unroll
      for (int i = 0; i < 4; i++) {
        float p = Ps[4 * ty + i][kj];
        O[i][0] += p * vv.x; O[i][1] += p * vv.y;
        O[i][2] += p * vv.z; O[i][3] += p * vv.w;
      }
    }
  }

  // Normalize + write [B,L,D]
  const int b = bh >> 4;
  const int h = bh & 15;
#pragma unroll
  for (int i = 0; i < 4; i++) {
    int l = q0 + 4 * ty + i;
    float inv = 1.0f / l_sum[i];
    float4 o = make_float4(O[i][0] * inv, O[i][1] * inv,
                           O[i][2] * inv, O[i][3] * inv);
    *(float4*)(g_attn + (size_t)(b * 2048 + l) * 1024 + h * 64 + 4 * tx) = o;
  }
}

// ---------------------------------------------------------------------------
// Proj GEMM: out[4096,1024] = g_attn @ proj_w^T + proj_b
// ---------------------------------------------------------------------------
__global__ __launch_bounds__(256) void proj_gemm_kernel(
    const float* __restrict__ W, const float* __restrict__ bias,
    float* __restrict__ out) {
  __shared__ float As[16][132];
  __shared__ float Bs[16][68];
  const int tid  = threadIdx.x;
  const int tx   = tid & 15;
  const int ty   = tid >> 4;
  const int row0 = blockIdx.y * 128;
  const int col0 = blockIdx.x * 64;
  const int lr   = tid >> 2;
  const int lc   = (tid & 3) * 4;

  float acc[8][4];
#pragma unroll
  for (int i = 0; i < 8; i++)
#pragma unroll
    for (int j = 0; j < 4; j++) acc[i][j] = 0.f;

  const float* Arow0 = g_attn + (size_t)(row0 + lr) * 1024 + lc;
  const float* Arow1 = g_attn + (size_t)(row0 + 64 + lr) * 1024 + lc;
  const float* Brow  = W + (size_t)(col0 + lr) * 1024 + lc;

  for (int k0 = 0; k0 < 1024; k0 += 16) {
    float4 a0 = *(const float4*)(Arow0 + k0);
    float4 a1 = *(const float4*)(Arow1 + k0);
    float4 b0 = *(const float4*)(Brow + k0);
    __syncthreads();
    As[lc + 0][lr] = a0.x; As[lc + 1][lr] = a0.y;
    As[lc + 2][lr] = a0.z; As[lc + 3][lr] = a0.w;
    As[lc + 0][64 + lr] = a1.x; As[lc + 1][64 + lr] = a1.y;
    As[lc + 2][64 + lr] = a1.z; As[lc + 3][64 + lr] = a1.w;
    Bs[lc + 0][lr] = b0.x; Bs[lc + 1][lr] = b0.y;
    Bs[lc + 2][lr] = b0.z; Bs[lc + 3][lr] = b0.w;
    __syncthreads();
#pragma unroll
    for (int k = 0; k < 16; k++) {
      float4 aA = *(const float4*)&As[k][ty * 8];
      float4 aB = *(const float4*)&As[k][ty * 8 + 4];
      float4 bb = *(const float4*)&Bs[k][tx * 4];
      float am[8] = {aA.x, aA.y, aA.z, aA.w, aB.x, aB.y, aB.z, aB.w};
      float bn[4] = {bb.x, bb.y, bb.z, bb.w};
#pragma unroll
      for (int i = 0; i < 8; i++)
#pragma unroll
        for (int j = 0; j < 4; j++) acc[i][j] += am[i] * bn[j];
    }
  }

  const int cbase = col0 + tx * 4;
  const float4 b4 = *(const float4*)(bias + cbase);
#pragma unroll
  for (int i = 0; i < 8; i++) {
    int gr = row0 + ty * 8 + i;
    float4 o = make_float4(acc[i][0] + b4.x, acc[i][1] + b4.y,
                           acc[i][2] + b4.z, acc[i][3] + b4.w);
    *(float4*)(out + (size_t)gr * 1024 + cbase) = o;
  }
}

// ---------------------------------------------------------------------------
extern "C" void kernel_launch(void* const* d_in, const int* in_sizes, int n_in,
                              void* d_out, int out_size) {
  const float* x      = (const float*)d_in[0];
  const float* qkv_w  = (const float*)d_in[1];
  const float* qkv_b  = (const float*)d_in[2];
  const float* proj_w = (const float*)d_in[3];
  const float* proj_b = (const float*)d_in[4];
  float* out = (float*)d_out;

  constexpr int ATTN_SMEM = 4 * 64 * 68 * (int)sizeof(float);  // 69632 B
  cudaFuncSetAttribute((const void*)attn_kernel,
                       cudaFuncAttributeMaxDynamicSharedMemorySize, ATTN_SMEM);

  qkv_gemm_kernel<<<dim3(48, 32), 256>>>(x, qkv_w, qkv_b);
  attn_kernel<<<dim3(32, 32), 256, ATTN_SMEM>>>();
  proj_gemm_kernel<<<dim3(16, 32), 256>>>(proj_w, proj_b, out);
}

// round 3
// speedup vs baseline: 3.3128x; 3.3128x over previous
#include <cuda_runtime.h>
#include <cuda_bf16.h>
#include <cstdint>

// Problem constants
static constexpr int Bc = 2, Lc = 2048, Dc = 1024, Hc = 16, HDc = 64;
static constexpr int Mc = Bc * Lc;  // 4096
static constexpr float SCALE = 0.125f;

// ---------------------------------------------------------------------------
// __device__ scratch (allocation-free rule). All bf16 hi/lo pairs.
// ---------------------------------------------------------------------------
__device__ __nv_bfloat16 g_xh[Mc * Dc], g_xl[Mc * Dc];           // x
__device__ __nv_bfloat16 g_wh[3 * Dc * Dc], g_wl[3 * Dc * Dc];   // qkv_w
__device__ __nv_bfloat16 g_pwh[Dc * Dc], g_pwl[Dc * Dc];         // proj_w
__device__ __nv_bfloat16 g_qh[Mc * Dc], g_ql[Mc * Dc];           // [B,H,L,Hd]
__device__ __nv_bfloat16 g_kh[Mc * Dc], g_kl[Mc * Dc];
__device__ __nv_bfloat16 g_vh[Mc * Dc], g_vl[Mc * Dc];
__device__ __nv_bfloat16 g_ah[Mc * Dc], g_al[Mc * Dc];           // attn out [B,L,D]

// ---------------------------------------------------------------------------
// helpers
// ---------------------------------------------------------------------------
__device__ __forceinline__ uint32_t smem_u32(const void* p) {
  uint32_t a;
  asm("{ .reg .u64 t; cvta.to.shared.u64 t, %1; cvt.u32.u64 %0, t; }"
      : "=r"(a) : "l"(p));
  return a;
}

__device__ __forceinline__ void mma16816(float* c, const uint32_t* a,
                                         const uint32_t* b) {
  asm volatile(
      "mma.sync.aligned.m16n8k16.row.col.f32.bf16.bf16.f32 "
      "{%0,%1,%2,%3}, {%4,%5,%6,%7}, {%8,%9}, {%0,%1,%2,%3};"
      : "+f"(c[0]), "+f"(c[1]), "+f"(c[2]), "+f"(c[3])
      : "r"(a[0]), "r"(a[1]), "r"(a[2]), "r"(a[3]), "r"(b[0]), "r"(b[1]));
}

__device__ __forceinline__ void ldsm_x4(uint32_t* r, uint32_t a) {
  asm volatile("ldmatrix.sync.aligned.m8n8.x4.shared.b16 {%0,%1,%2,%3}, [%4];"
               : "=r"(r[0]), "=r"(r[1]), "=r"(r[2]), "=r"(r[3]) : "r"(a));
}
__device__ __forceinline__ void ldsm_x2(uint32_t* r, uint32_t a) {
  asm volatile("ldmatrix.sync.aligned.m8n8.x2.shared.b16 {%0,%1}, [%2];"
               : "=r"(r[0]), "=r"(r[1]) : "r"(a));
}
__device__ __forceinline__ void ldsm_x2_t(uint32_t* r, uint32_t a) {
  asm volatile("ldmatrix.sync.aligned.m8n8.x2.trans.shared.b16 {%0,%1}, [%2];"
               : "=r"(r[0]), "=r"(r[1]) : "r"(a));
}

// split two fp32 into packed bf16x2 hi + residual lo
__device__ __forceinline__ void split_pack(float x, float y, uint32_t& hi,
                                           uint32_t& lo) {
  __nv_bfloat16 hx = __float2bfloat16(x), hy = __float2bfloat16(y);
  __nv_bfloat162 hp(hx, hy);
  hi = *reinterpret_cast<uint32_t*>(&hp);
  __nv_bfloat162 lp(__float2bfloat16(x - __bfloat162float(hx)),
                    __float2bfloat16(y - __bfloat162float(hy)));
  lo = *reinterpret_cast<uint32_t*>(&lp);
}

// ---------------------------------------------------------------------------
// fp32 -> bf16 hi/lo conversion. which: 0=x, 1=qkv_w, 2=proj_w
// ---------------------------------------------------------------------------
__global__ __launch_bounds__(256) void convert_hilo(const float* __restrict__ src,
                                                    int which, int n4) {
  int i = blockIdx.x * 256 + threadIdx.x;
  if (i >= n4) return;
  __nv_bfloat16 *hi, *lo;
  if (which == 0)      { hi = g_xh;  lo = g_xl; }
  else if (which == 1) { hi = g_wh;  lo = g_wl; }
  else                 { hi = g_pwh; lo = g_pwl; }
  float4 v = ((const float4*)src)[i];
  uint32_t h0, l0, h1, l1;
  split_pack(v.x, v.y, h0, l0);
  split_pack(v.z, v.w, h1, l1);
  ((uint32_t*)hi)[2 * i] = h0; ((uint32_t*)hi)[2 * i + 1] = h1;
  ((uint32_t*)lo)[2 * i] = l0; ((uint32_t*)lo)[2 * i + 1] = l1;
}

// ---------------------------------------------------------------------------
// HMMA GEMM: C[m,n] = sum_k A[m,k]*W[n,k] + bias[n]   (K = 1024)
// MODE 0: A = x hi/lo,   W = qkv_w hi/lo -> bf16 hi/lo scatter into q/k/v
// MODE 1: A = attn hi/lo, W = proj_w hi/lo -> fp32 out
// Block 128x128, 256 thr (8 warps: 4m x 2n, warp tile 32x64).
// K-chunks of 64, cp.async double-buffered. 3-pass hi/lo.
// SMEM stage: Ah|Al|Bh|Bl, each 128 rows x 144B (72 bf16, 8-elem pad).
// ---------------------------------------------------------------------------
static constexpr int GARR = 18432;          // bytes per array
static constexpr int GSTAGE = 4 * GARR;     // 73728
static constexpr int GEMM_SMEM = 2 * GSTAGE;

template <int MODE>
__global__ __launch_bounds__(256) void hmma_gemm(const float* __restrict__ bias,
                                                 float* __restrict__ out) {
  extern __shared__ char smraw[];
  const int tid = threadIdx.x, lane = tid & 31, wid = tid >> 5;
  const int wm = wid & 3, wn = wid >> 2;
  const int n0 = blockIdx.x * 128, m0 = blockIdx.y * 128;
  const uint32_t sbase = smem_u32(smraw);

  const __nv_bfloat16* A0 = (MODE == 0) ? g_xh : g_ah;
  const __nv_bfloat16* A1 = (MODE == 0) ? g_xl : g_al;
  const __nv_bfloat16* B0 = (MODE == 0) ? g_wh : g_pwh;
  const __nv_bfloat16* B1 = (MODE == 0) ? g_wl : g_pwl;

  auto issue = [&](int kc) {
    const int s = kc & 1;
    const int k0 = kc * 64;
    const uint32_t sb = sbase + s * GSTAGE;
#pragma unroll
    for (int arr = 0; arr < 4; arr++) {
      const __nv_bfloat16* g =
          (arr == 0) ? A0 : (arr == 1) ? A1 : (arr == 2) ? B0 : B1;
      const int r0 = (arr < 2) ? m0 : n0;
      const uint32_t dbase = sb + arr * GARR;
#pragma unroll
      for (int it = 0; it < 4; it++) {
        int u = tid + it * 256;       // 0..1023
        int r = u >> 3, c8 = u & 7;   // row, 16B-chunk within 128B row
        const void* gp = g + (size_t)(r0 + r) * 1024 + k0 + c8 * 8;
        uint32_t sp = dbase + r * 144 + c8 * 16;
        asm volatile("cp.async.cg.shared.global [%0], [%1], 16;"
                     :: "r"(sp), "l"(gp) : "memory");
      }
    }
    asm volatile("cp.async.commit_group;" ::: "memory");
  };

  float c[2][8][4];
#pragma unroll
  for (int mt = 0; mt < 2; mt++)
#pragma unroll
    for (int nt = 0; nt < 8; nt++)
#pragma unroll
      for (int e = 0; e < 4; e++) c[mt][nt][e] = 0.f;

  issue(0);
  for (int kc = 0; kc < 16; kc++) {
    if (kc + 1 < 16) {
      issue(kc + 1);
      asm volatile("cp.async.wait_group 1;" ::: "memory");
    } else {
      asm volatile("cp.async.wait_group 0;" ::: "memory");
    }
    __syncthreads();
    const uint32_t sb = sbase + (kc & 1) * GSTAGE;
#pragma unroll
    for (int ks = 0; ks < 4; ks++) {
      const int kk = ks * 16;
      uint32_t ah[2][4], al[2][4];
#pragma unroll
      for (int mt = 0; mt < 2; mt++) {
        int row = wm * 32 + mt * 16 + (lane & 15);
        uint32_t a = sb + row * 144 + (kk + (lane >> 4) * 8) * 2;
        ldsm_x4(ah[mt], a);
        ldsm_x4(al[mt], a + GARR);
      }
#pragma unroll
      for (int nt = 0; nt < 8; nt++) {
        int row = wn * 64 + nt * 8 + (lane & 7);
        uint32_t a = sb + 2 * GARR + row * 144 +
                     (kk + ((lane >> 3) & 1) * 8) * 2;
        uint32_t bh[2], bl[2];
        ldsm_x2(bh, a);
        ldsm_x2(bl, a + GARR);
#pragma unroll
        for (int mt = 0; mt < 2; mt++) {
          mma16816(c[mt][nt], ah[mt], bh);
          mma16816(c[mt][nt], ah[mt], bl);
          mma16816(c[mt][nt], al[mt], bh);
        }
      }
    }
    __syncthreads();
  }

  // Epilogue
#pragma unroll
  for (int mt = 0; mt < 2; mt++) {
#pragma unroll
    for (int half = 0; half < 2; half++) {
      const int m = m0 + wm * 32 + mt * 16 + (lane >> 2) + half * 8;
#pragma unroll
      for (int nt = 0; nt < 8; nt++) {
        const int n = n0 + wn * 64 + nt * 8 + (lane & 3) * 2;
        float v0 = c[mt][nt][half * 2 + 0] + bias[n];
        float v1 = c[mt][nt][half * 2 + 1] + bias[n + 1];
        if (MODE == 0) {
          const int three = n >> 10;
          const int h = (n & 1023) >> 6;
          const int d = n & 63;
          const int b = m >> 11, l = m & 2047;
          size_t idx = ((size_t)((b * 16 + h) * 2048 + l)) * 64 + d;
          uint32_t hv, lv;
          split_pack(v0, v1, hv, lv);
          __nv_bfloat16 *ph, *pl;
          if (three == 0)      { ph = g_qh; pl = g_ql; }
          else if (three == 1) { ph = g_kh; pl = g_kl; }
          else                 { ph = g_vh; pl = g_vl; }
          *(uint32_t*)(ph + idx) = hv;
          *(uint32_t*)(pl + idx) = lv;
        } else {
          *(float2*)(out + (size_t)m * 1024 + n) = make_float2(v0, v1);
        }
      }
    }
  }
}

// ---------------------------------------------------------------------------
// Flash attention on HMMA. Block = (q-tile 64, bh), 128 thr (4 warps).
// Warp owns 16 q rows. QK^T 3-pass hi/lo; softmax fp32 in fragments;
// P.V 3-pass with P split in registers, V via ldmatrix.trans.
// SMEM: Qh|Ql|Kh|Kl|Vh|Vl, each 64 rows x 144B = 9216B, total 55296B.
// ---------------------------------------------------------------------------
static constexpr int AARR = 9216;
static constexpr int ATTN_SMEM = 6 * AARR;

__global__ __launch_bounds__(128) void attn_mma() {
  extern __shared__ char smraw[];
  const int tid = threadIdx.x, lane = tid & 31, wid = tid >> 5;
  const int q0 = blockIdx.x * 64, bh = blockIdx.y;
  const uint32_t sb = smem_u32(smraw);

  // Load Q hi/lo (64 x 64 bf16 each)
  const size_t qoff = ((size_t)bh * 2048 + q0) * 64;
#pragma unroll
  for (int it = 0; it < 4; it++) {
    int u = tid + it * 128;
    int r = u >> 3, c8 = u & 7;
    uint32_t so = r * 144 + c8 * 16;
    size_t go = qoff + r * 64 + c8 * 8;
    *(uint4*)(smraw + so)        = *(const uint4*)(g_qh + go);
    *(uint4*)(smraw + AARR + so) = *(const uint4*)(g_ql + go);
  }

  float o[8][4];
  float m_s[2] = {-1e30f, -1e30f}, l_s[2] = {0.f, 0.f};
#pragma unroll
  for (int nt = 0; nt < 8; nt++)
#pragma unroll
    for (int e = 0; e < 4; e++) o[nt][e] = 0.f;

  for (int kt = 0; kt < 32; kt++) {
    __syncthreads();
    const size_t koff = ((size_t)bh * 2048 + kt * 64) * 64;
#pragma unroll
    for (int it = 0; it < 4; it++) {
      int u = tid + it * 128;
      int r = u >> 3, c8 = u & 7;
      uint32_t so = r * 144 + c8 * 16;
      size_t go = koff + r * 64 + c8 * 8;
      *(uint4*)(smraw + 2 * AARR + so) = *(const uint4*)(g_kh + go);
      *(uint4*)(smraw + 3 * AARR + so) = *(const uint4*)(g_kl + go);
      *(uint4*)(smraw + 4 * AARR + so) = *(const uint4*)(g_vh + go);
      *(uint4*)(smraw + 5 * AARR + so) = *(const uint4*)(g_vl + go);
    }
    __syncthreads();

    // S = Q K^T (64 keys), 3-pass
    float s[8][4];
#pragma unroll
    for (int nt = 0; nt < 8; nt++)
#pragma unroll
      for (int e = 0; e < 4; e++) s[nt][e] = 0.f;

#pragma unroll
    for (int ks = 0; ks < 4; ks++) {
      const int kk = ks * 16;
      uint32_t ah[4], al[4];
      {
        int row = wid * 16 + (lane & 15);
        uint32_t a = sb + row * 144 + (kk + (lane >> 4) * 8) * 2;
        ldsm_x4(ah, a);
        ldsm_x4(al, a + AARR);
      }
#pragma unroll
      for (int nt = 0; nt < 8; nt++) {
        int row = nt * 8 + (lane & 7);
        uint32_t a = sb + 2 * AARR + row * 144 +
                     (kk + ((lane >> 3) & 1) * 8) * 2;
        uint32_t bhf[2], blf[2];
        ldsm_x2(bhf, a);
        ldsm_x2(blf, a + AARR);
        mma16816(s[nt], ah, bhf);
        mma16816(s[nt], ah, blf);
        mma16816(s[nt], al, bhf);
      }
    }

    // Online softmax (rows r=lane/4 and r+8; quad = lanes {xor1, xor2})
#pragma unroll
    for (int half = 0; half < 2; half++) {
      float mx = -1e30f;
#pragma unroll
      for (int nt = 0; nt < 8; nt++) {
        s[nt][half * 2]     *= SCALE;
        s[nt][half * 2 + 1] *= SCALE;
        mx = fmaxf(mx, fmaxf(s[nt][half * 2], s[nt][half * 2 + 1]));
      }
      mx = fmaxf(mx, __shfl_xor_sync(0xffffffffu, mx, 1));
      mx = fmaxf(mx, __shfl_xor_sync(0xffffffffu, mx, 2));
      float mn = fmaxf(m_s[half], mx);
      float alpha = __expf(m_s[half] - mn);
      float ps = 0.f;
#pragma unroll
      for (int nt = 0; nt < 8; nt++) {
        float p0 = __expf(s[nt][half * 2] - mn);
        float p1 = __expf(s[nt][half * 2 + 1] - mn);
        s[nt][half * 2] = p0;
        s[nt][half * 2 + 1] = p1;
        ps += p0 + p1;
      }
      ps += __shfl_xor_sync(0xffffffffu, ps, 1);
      ps += __shfl_xor_sync(0xffffffffu, ps, 2);
      l_s[half] = l_s[half] * alpha + ps;
      m_s[half] = mn;
#pragma unroll
      for (int nt = 0; nt < 8; nt++) {
        o[nt][half * 2]     *= alpha;
        o[nt][half * 2 + 1] *= alpha;
      }
    }

    // O += P V, 3-pass (P hi/lo in regs, V hi/lo via ldmatrix.trans)
#pragma unroll
    for (int ks = 0; ks < 4; ks++) {
      const int t0 = 2 * ks, t1 = 2 * ks + 1;
      uint32_t pah[4], pal[4];
      split_pack(s[t0][0], s[t0][1], pah[0], pal[0]);
      split_pack(s[t0][2], s[t0][3], pah[1], pal[1]);
      split_pack(s[t1][0], s[t1][1], pah[2], pal[2]);
      split_pack(s[t1][2], s[t1][3], pah[3], pal[3]);
      int row = ks * 16 + (lane & 7) + ((lane >> 3) & 1) * 8;
#pragma unroll
      for (int nt = 0; nt < 8; nt++) {
        uint32_t a = sb + 4 * AARR + row * 144 + nt * 16;
        uint32_t bvh[2], bvl[2];
        ldsm_x2_t(bvh, a);
        ldsm_x2_t(bvl, a + AARR);
        mma16816(o[nt], pah, bvh);
        mma16816(o[nt], pal, bvh);
        mma16816(o[nt], pah, bvl);
      }
    }
  }

  // Epilogue: normalize, split hi/lo, write [B,L,D]
  const int b = bh >> 4, h = bh & 15;
#pragma unroll
  for (int half = 0; half < 2; half++) {
    const int row = q0 + wid * 16 + (lane >> 2) + half * 8;
    const float inv = 1.0f / l_s[half];
    const size_t base = ((size_t)(b * 2048 + row)) * 1024 + h * 64;
#pragma unroll
    for (int nt = 0; nt < 8; nt++) {
      const int d = nt * 8 + (lane & 3) * 2;
      float v0 = o[nt][half * 2] * inv;
      float v1 = o[nt][half * 2 + 1] * inv;
      uint32_t hv, lv;
      split_pack(v0, v1, hv, lv);
      *(uint32_t*)(g_ah + base + d) = hv;
      *(uint32_t*)(g_al + base + d) = lv;
    }
  }
}

// ---------------------------------------------------------------------------
extern "C" void kernel_launch(void* const* d_in, const int* in_sizes, int n_in,
                              void* d_out, int out_size) {
  const float* x      = (const float*)d_in[0];
  const float* qkv_w  = (const float*)d_in[1];
  const float* qkv_b  = (const float*)d_in[2];
  const float* proj_w = (const float*)d_in[3];
  const float* proj_b = (const float*)d_in[4];
  float* out = (float*)d_out;

  cudaFuncSetAttribute((const void*)hmma_gemm<0>,
                       cudaFuncAttributeMaxDynamicSharedMemorySize, GEMM_SMEM);
  cudaFuncSetAttribute((const void*)hmma_gemm<1>,
                       cudaFuncAttributeMaxDynamicSharedMemorySize, GEMM_SMEM);
  cudaFuncSetAttribute((const void*)attn_mma,
                       cudaFuncAttributeMaxDynamicSharedMemorySize, ATTN_SMEM);

  convert_hilo<<<Mc * Dc / 4 / 256, 256>>>(x, 0, Mc * Dc / 4);
  convert_hilo<<<3 * Dc * Dc / 4 / 256, 256>>>(qkv_w, 1, 3 * Dc * Dc / 4);
  convert_hilo<<<Dc * Dc / 4 / 256, 256>>>(proj_w, 2, Dc * Dc / 4);

  hmma_gemm<0><<<dim3(24, 32), 256, GEMM_SMEM>>>(qkv_b, nullptr);
  attn_mma<<<dim3(32, 32), 128, ATTN_SMEM>>>();
  hmma_gemm<1><<<dim3(8, 32), 256, GEMM_SMEM>>>(proj_b, out);
}

// round 5
// speedup vs baseline: 3.3342x; 1.0065x over previous
#include <cuda_runtime.h>
#include <cuda_bf16.h>
#include <cstdint>

// Problem constants
static constexpr int Bc = 2, Lc = 2048, Dc = 1024, Hc = 16, HDc = 64;
static constexpr int Mc = Bc * Lc;  // 4096
static constexpr float SCALE = 0.125f;

// ---------------------------------------------------------------------------
// __device__ scratch (allocation-free rule). All bf16 hi/lo pairs.
// ---------------------------------------------------------------------------
__device__ __nv_bfloat16 g_xh[Mc * Dc], g_xl[Mc * Dc];           // x
__device__ __nv_bfloat16 g_wh[3 * Dc * Dc], g_wl[3 * Dc * Dc];   // qkv_w
__device__ __nv_bfloat16 g_pwh[Dc * Dc], g_pwl[Dc * Dc];         // proj_w
__device__ __nv_bfloat16 g_qh[Mc * Dc], g_ql[Mc * Dc];           // [B,H,L,Hd]
__device__ __nv_bfloat16 g_kh[Mc * Dc], g_kl[Mc * Dc];
__device__ __nv_bfloat16 g_vh[Mc * Dc], g_vl[Mc * Dc];
__device__ __nv_bfloat16 g_ah[Mc * Dc], g_al[Mc * Dc];           // attn out [B,L,D]

// ---------------------------------------------------------------------------
// helpers
// ---------------------------------------------------------------------------
__device__ __forceinline__ uint32_t smem_u32(const void* p) {
  uint32_t a;
  asm("{ .reg .u64 t; cvta.to.shared.u64 t, %1; cvt.u32.u64 %0, t; }"
      : "=r"(a) : "l"(p));
  return a;
}

__device__ __forceinline__ void mma16816(float* c, const uint32_t* a,
                                         const uint32_t* b) {
  asm volatile(
      "mma.sync.aligned.m16n8k16.row.col.f32.bf16.bf16.f32 "
      "{%0,%1,%2,%3}, {%4,%5,%6,%7}, {%8,%9}, {%0,%1,%2,%3};"
      : "+f"(c[0]), "+f"(c[1]), "+f"(c[2]), "+f"(c[3])
      : "r"(a[0]), "r"(a[1]), "r"(a[2]), "r"(a[3]), "r"(b[0]), "r"(b[1]));
}

__device__ __forceinline__ void ldsm_x4(uint32_t* r, uint32_t a) {
  asm volatile("ldmatrix.sync.aligned.m8n8.x4.shared.b16 {%0,%1,%2,%3}, [%4];"
               : "=r"(r[0]), "=r"(r[1]), "=r"(r[2]), "=r"(r[3]) : "r"(a));
}
__device__ __forceinline__ void ldsm_x2(uint32_t* r, uint32_t a) {
  asm volatile("ldmatrix.sync.aligned.m8n8.x2.shared.b16 {%0,%1}, [%2];"
               : "=r"(r[0]), "=r"(r[1]) : "r"(a));
}
__device__ __forceinline__ void ldsm_x2_t(uint32_t* r, uint32_t a) {
  asm volatile("ldmatrix.sync.aligned.m8n8.x2.trans.shared.b16 {%0,%1}, [%2];"
               : "=r"(r[0]), "=r"(r[1]) : "r"(a));
}

__device__ __forceinline__ void cpasync16(uint32_t sp, const void* gp) {
  asm volatile("cp.async.cg.shared.global [%0], [%1], 16;"
               :: "r"(sp), "l"(gp) : "memory");
}

// split two fp32 into packed bf16x2 hi + residual lo
__device__ __forceinline__ void split_pack(float x, float y, uint32_t& hi,
                                           uint32_t& lo) {
  __nv_bfloat16 hx = __float2bfloat16(x), hy = __float2bfloat16(y);
  __nv_bfloat162 hp(hx, hy);
  hi = *reinterpret_cast<uint32_t*>(&hp);
  __nv_bfloat162 lp(__float2bfloat16(x - __bfloat162float(hx)),
                    __float2bfloat16(y - __bfloat162float(hy)));
  lo = *reinterpret_cast<uint32_t*>(&lp);
}

// ---------------------------------------------------------------------------
// fp32 -> bf16 hi/lo conversion. which: 0=x, 1=qkv_w, 2=proj_w
// ---------------------------------------------------------------------------
__global__ __launch_bounds__(256) void convert_hilo(const float* __restrict__ src,
                                                    int which, int n4) {
  int i = blockIdx.x * 256 + threadIdx.x;
  if (i >= n4) return;
  __nv_bfloat16 *hi, *lo;
  if (which == 0)      { hi = g_xh;  lo = g_xl; }
  else if (which == 1) { hi = g_wh;  lo = g_wl; }
  else                 { hi = g_pwh; lo = g_pwl; }
  float4 v = ((const float4*)src)[i];
  uint32_t h0, l0, h1, l1;
  split_pack(v.x, v.y, h0, l0);
  split_pack(v.z, v.w, h1, l1);
  ((uint32_t*)hi)[2 * i] = h0; ((uint32_t*)hi)[2 * i + 1] = h1;
  ((uint32_t*)lo)[2 * i] = l0; ((uint32_t*)lo)[2 * i + 1] = l1;
}

// ---------------------------------------------------------------------------
// HMMA GEMM: C[m,n] = sum_k A[m,k]*W[n,k] + bias[n]   (K = 1024)
// MODE 0: A = x hi/lo,   W = qkv_w hi/lo -> bf16 hi/lo scatter into q/k/v
// MODE 1: A = attn hi/lo, W = proj_w hi/lo -> fp32 out
// Block 128x128, 256 thr (8 warps: 4m x 2n, warp tile 32x64).
// K-chunks of 32 (small stage => 2 CTAs/SM), cp.async double-buffered.
// 3-pass hi/lo. SMEM rows padded to 80B (conflict-free ldmatrix).
// ---------------------------------------------------------------------------
static constexpr int GROW = 80;             // 32 bf16 (64B) + 16B pad
static constexpr int GARR = 128 * GROW;     // 10240
static constexpr int GSTAGE = 4 * GARR;     // 40960
static constexpr int GEMM_SMEM = 2 * GSTAGE;  // 81920

template <int MODE>
__global__ __launch_bounds__(256, 2) void hmma_gemm(const float* __restrict__ bias,
                                                    float* __restrict__ out) {
  extern __shared__ char smraw[];
  const int tid = threadIdx.x, lane = tid & 31, wid = tid >> 5;
  const int wm = wid & 3, wn = wid >> 2;
  const int n0 = blockIdx.x * 128, m0 = blockIdx.y * 128;
  const uint32_t sbase = smem_u32(smraw);

  const __nv_bfloat16* A0 = (MODE == 0) ? g_xh : g_ah;
  const __nv_bfloat16* A1 = (MODE == 0) ? g_xl : g_al;
  const __nv_bfloat16* B0 = (MODE == 0) ? g_wh : g_pwh;
  const __nv_bfloat16* B1 = (MODE == 0) ? g_wl : g_pwl;

  auto issue = [&](int kc) {
    const int k0 = kc * 32;
    const uint32_t sb = sbase + (kc & 1) * GSTAGE;
#pragma unroll
    for (int arr = 0; arr < 4; arr++) {
      const __nv_bfloat16* g =
          (arr == 0) ? A0 : (arr == 1) ? A1 : (arr == 2) ? B0 : B1;
      const int r0 = (arr < 2) ? m0 : n0;
      const uint32_t dbase = sb + arr * GARR;
#pragma unroll
      for (int it = 0; it < 2; it++) {
        int u = tid + it * 256;       // 0..511
        int r = u >> 2, c4 = u & 3;   // row, 16B chunk within 64B row
        cpasync16(dbase + r * GROW + c4 * 16,
                  g + (size_t)(r0 + r) * 1024 + k0 + c4 * 8);
      }
    }
    asm volatile("cp.async.commit_group;" ::: "memory");
  };

  float c[2][8][4];
#pragma unroll
  for (int mt = 0; mt < 2; mt++)
#pragma unroll
    for (int nt = 0; nt < 8; nt++)
#pragma unroll
      for (int e = 0; e < 4; e++) c[mt][nt][e] = 0.f;

  issue(0);
  for (int kc = 0; kc < 32; kc++) {
    if (kc + 1 < 32) {
      issue(kc + 1);
      asm volatile("cp.async.wait_group 1;" ::: "memory");
    } else {
      asm volatile("cp.async.wait_group 0;" ::: "memory");
    }
    __syncthreads();
    const uint32_t sb = sbase + (kc & 1) * GSTAGE;
#pragma unroll
    for (int ks = 0; ks < 2; ks++) {
      const int kk = ks * 16;
      uint32_t ah[2][4], al[2][4];
#pragma unroll
      for (int mt = 0; mt < 2; mt++) {
        int row = wm * 32 + mt * 16 + (lane & 15);
        uint32_t a = sb + row * GROW + (kk + (lane >> 4) * 8) * 2;
        ldsm_x4(ah[mt], a);
        ldsm_x4(al[mt], a + GARR);
      }
#pragma unroll
      for (int nt = 0; nt < 8; nt++) {
        int row = wn * 64 + nt * 8 + (lane & 7);
        uint32_t a = sb + 2 * GARR + row * GROW +
                     (kk + ((lane >> 3) & 1) * 8) * 2;
        uint32_t bh[2], bl[2];
        ldsm_x2(bh, a);
        ldsm_x2(bl, a + GARR);
#pragma unroll
        for (int mt = 0; mt < 2; mt++) {
          mma16816(c[mt][nt], ah[mt], bh);
          mma16816(c[mt][nt], ah[mt], bl);
          mma16816(c[mt][nt], al[mt], bh);
        }
      }
    }
    __syncthreads();
  }

  // Epilogue
#pragma unroll
  for (int mt = 0; mt < 2; mt++) {
#pragma unroll
    for (int half = 0; half < 2; half++) {
      const int m = m0 + wm * 32 + mt * 16 + (lane >> 2) + half * 8;
#pragma unroll
      for (int nt = 0; nt < 8; nt++) {
        const int n = n0 + wn * 64 + nt * 8 + (lane & 3) * 2;
        float v0 = c[mt][nt][half * 2 + 0] + bias[n];
        float v1 = c[mt][nt][half * 2 + 1] + bias[n + 1];
        if (MODE == 0) {
          const int three = n >> 10;
          const int h = (n & 1023) >> 6;
          const int d = n & 63;
          const int b = m >> 11, l = m & 2047;
          size_t idx = ((size_t)((b * 16 + h) * 2048 + l)) * 64 + d;
          uint32_t hv, lv;
          split_pack(v0, v1, hv, lv);
          __nv_bfloat16 *ph, *pl;
          if (three == 0)      { ph = g_qh; pl = g_ql; }
          else if (three == 1) { ph = g_kh; pl = g_kl; }
          else                 { ph = g_vh; pl = g_vl; }
          *(uint32_t*)(ph + idx) = hv;
          *(uint32_t*)(pl + idx) = lv;
        } else {
          *(float2*)(out + (size_t)m * 1024 + n) = make_float2(v0, v1);
        }
      }
    }
  }
}

// ---------------------------------------------------------------------------
// Flash attention on HMMA. Block = (q-tile 128, bh), 256 thr (8 warps).
// Warp owns 16 q rows. QK^T 3-pass hi/lo; softmax fp32; P.V 3-pass.
// K/V cp.async double-buffered.
// SMEM: Qh|Ql (128x144) + 2 stages x (Kh|Kl|Vh|Vl, each 64x144).
// ---------------------------------------------------------------------------
static constexpr int AROW = 144;
static constexpr int AKV = 64 * AROW;               // 9216
static constexpr int AQ = 128 * AROW;               // 18432
static constexpr int ASTAGE = 4 * AKV;              // 36864
static constexpr int ATTN_SMEM = 2 * AQ + 2 * ASTAGE;  // 110592

__global__ __launch_bounds__(256, 2) void attn_mma() {
  extern __shared__ char smraw[];
  const int tid = threadIdx.x, lane = tid & 31, wid = tid >> 5;
  const int q0 = blockIdx.x * 128, bh = blockIdx.y;
  const uint32_t sb = smem_u32(smraw);
  const uint32_t kvbase = sb + 2 * AQ;

  // Load Q hi/lo (128 x 64 bf16 each) via cp.async
  const size_t qoff = ((size_t)bh * 2048 + q0) * 64;
#pragma unroll
  for (int it = 0; it < 4; it++) {
    int u = tid + it * 256;          // 0..1023
    int r = u >> 3, c8 = u & 7;
    uint32_t so = r * AROW + c8 * 16;
    size_t go = qoff + r * 64 + c8 * 8;
    cpasync16(sb + so, g_qh + go);
    cpasync16(sb + AQ + so, g_ql + go);
  }
  asm volatile("cp.async.commit_group;" ::: "memory");

  auto issue_kv = [&](int kt) {
    const uint32_t st = kvbase + (kt & 1) * ASTAGE;
    const size_t koff = ((size_t)bh * 2048 + kt * 64) * 64;
#pragma unroll
    for (int it = 0; it < 2; it++) {
      int u = tid + it * 256;        // 0..511
      int r = u >> 3, c8 = u & 7;
      uint32_t so = r * AROW + c8 * 16;
      size_t go = koff + r * 64 + c8 * 8;
      cpasync16(st + so,            g_kh + go);
      cpasync16(st + AKV + so,      g_kl + go);
      cpasync16(st + 2 * AKV + so,  g_vh + go);
      cpasync16(st + 3 * AKV + so,  g_vl + go);
    }
    asm volatile("cp.async.commit_group;" ::: "memory");
  };

  float o[8][4];
  float m_s[2] = {-1e30f, -1e30f}, l_s[2] = {0.f, 0.f};
#pragma unroll
  for (int nt = 0; nt < 8; nt++)
#pragma unroll
    for (int e = 0; e < 4; e++) o[nt][e] = 0.f;

  issue_kv(0);

  for (int kt = 0; kt < 32; kt++) {
    if (kt + 1 < 32) {
      issue_kv(kt + 1);
      asm volatile("cp.async.wait_group 1;" ::: "memory");
    } else {
      asm volatile("cp.async.wait_group 0;" ::: "memory");
    }
    __syncthreads();
    const uint32_t st = kvbase + (kt & 1) * ASTAGE;

    // S = Q K^T (64 keys), 3-pass
    float s[8][4];
#pragma unroll
    for (int nt = 0; nt < 8; nt++)
#pragma unroll
      for (int e = 0; e < 4; e++) s[nt][e] = 0.f;

#pragma unroll
    for (int ks = 0; ks < 4; ks++) {
      const int kk = ks * 16;
      uint32_t ah[4], al[4];
      {
        int row = wid * 16 + (lane & 15);
        uint32_t a = sb + row * AROW + (kk + (lane >> 4) * 8) * 2;
        ldsm_x4(ah, a);
        ldsm_x4(al, a + AQ);
      }
#pragma unroll
      for (int nt = 0; nt < 8; nt++) {
        int row = nt * 8 + (lane & 7);
        uint32_t a = st + row * AROW + (kk + ((lane >> 3) & 1) * 8) * 2;
        uint32_t bhf[2], blf[2];
        ldsm_x2(bhf, a);
        ldsm_x2(blf, a + AKV);
        mma16816(s[nt], ah, bhf);
        mma16816(s[nt], ah, blf);
        mma16816(s[nt], al, bhf);
      }
    }

    // Online softmax (rows r=lane/4 and r+8; quad reduce over lanes xor1,xor2)
#pragma unroll
    for (int half = 0; half < 2; half++) {
      float mx = -1e30f;
#pragma unroll
      for (int nt = 0; nt < 8; nt++) {
        s[nt][half * 2]     *= SCALE;
        s[nt][half * 2 + 1] *= SCALE;
        mx = fmaxf(mx, fmaxf(s[nt][half * 2], s[nt][half * 2 + 1]));
      }
      mx = fmaxf(mx, __shfl_xor_sync(0xffffffffu, mx, 1));
      mx = fmaxf(mx, __shfl_xor_sync(0xffffffffu, mx, 2));
      float mn = fmaxf(m_s[half], mx);
      float alpha = __expf(m_s[half] - mn);
      float ps = 0.f;
#pragma unroll
      for (int nt = 0; nt < 8; nt++) {
        float p0 = __expf(s[nt][half * 2] - mn);
        float p1 = __expf(s[nt][half * 2 + 1] - mn);
        s[nt][half * 2] = p0;
        s[nt][half * 2 + 1] = p1;
        ps += p0 + p1;
      }
      ps += __shfl_xor_sync(0xffffffffu, ps, 1);
      ps += __shfl_xor_sync(0xffffffffu, ps, 2);
      l_s[half] = l_s[half] * alpha + ps;
      m_s[half] = mn;
#pragma unroll
      for (int nt = 0; nt < 8; nt++) {
        o[nt][half * 2]     *= alpha;
        o[nt][half * 2 + 1] *= alpha;
      }
    }

    // O += P V, 3-pass (P hi/lo in regs, V hi/lo via ldmatrix.trans)
#pragma unroll
    for (int ks = 0; ks < 4; ks++) {
      const int t0 = 2 * ks, t1 = 2 * ks + 1;
      uint32_t pah[4], pal[4];
      split_pack(s[t0][0], s[t0][1], pah[0], pal[0]);
      split_pack(s[t0][2], s[t0][3], pah[1], pal[1]);
      split_pack(s[t1][0], s[t1][1], pah[2], pal[2]);
      split_pack(s[t1][2], s[t1][3], pah[3], pal[3]);
      int row = ks * 16 + (lane & 7) + ((lane >> 3) & 1) * 8;
#pragma unroll
      for (int nt = 0; nt < 8; nt++) {
        uint32_t a = st + 2 * AKV + row * AROW + nt * 16;
        uint32_t bvh[2], bvl[2];
        ldsm_x2_t(bvh, a);
        ldsm_x2_t(bvl, a + AKV);
        mma16816(o[nt], pah, bvh);
        mma16816(o[nt], pal, bvh);
        mma16816(o[nt], pah, bvl);
      }
    }
    __syncthreads();
  }

  // Epilogue: normalize, split hi/lo, write [B,L,D]
  const int b = bh >> 4, h = bh & 15;
#pragma unroll
  for (int half = 0; half < 2; half++) {
    const int row = q0 + wid * 16 + (lane >> 2) + half * 8;
    const float inv = 1.0f / l_s[half];
    const size_t base = ((size_t)(b * 2048 + row)) * 1024 + h * 64;
#pragma unroll
    for (int nt = 0; nt < 8; nt++) {
      const int d = nt * 8 + (lane & 3) * 2;
      float v0 = o[nt][half * 2] * inv;
      float v1 = o[nt][half * 2 + 1] * inv;
      uint32_t hv, lv;
      split_pack(v0, v1, hv, lv);
      *(uint32_t*)(g_ah + base + d) = hv;
      *(uint32_t*)(g_al + base + d) = lv;
    }
  }
}

// ---------------------------------------------------------------------------
extern "C" void kernel_launch(void* const* d_in, const int* in_sizes, int n_in,
                              void* d_out, int out_size) {
  const float* x      = (const float*)d_in[0];
  const float* qkv_w  = (const float*)d_in[1];
  const float* qkv_b  = (const float*)d_in[2];
  const float* proj_w = (const float*)d_in[3];
  const float* proj_b = (const float*)d_in[4];
  float* out = (float*)d_out;

  cudaFuncSetAttribute((const void*)hmma_gemm<0>,
                       cudaFuncAttributeMaxDynamicSharedMemorySize, GEMM_SMEM);
  cudaFuncSetAttribute((const void*)hmma_gemm<1>,
                       cudaFuncAttributeMaxDynamicSharedMemorySize, GEMM_SMEM);
  cudaFuncSetAttribute((const void*)attn_mma,
                       cudaFuncAttributeMaxDynamicSharedMemorySize, ATTN_SMEM);

  convert_hilo<<<Mc * Dc / 4 / 256, 256>>>(x, 0, Mc * Dc / 4);
  convert_hilo<<<3 * Dc * Dc / 4 / 256, 256>>>(qkv_w, 1, 3 * Dc * Dc / 4);
  convert_hilo<<<Dc * Dc / 4 / 256, 256>>>(proj_w, 2, Dc * Dc / 4);

  hmma_gemm<0><<<dim3(24, 32), 256, GEMM_SMEM>>>(qkv_b, nullptr);
  attn_mma<<<dim3(16, 32), 256, ATTN_SMEM>>>();
  hmma_gemm<1><<<dim3(8, 32), 256, GEMM_SMEM>>>(proj_b, out);
}

// round 6
// speedup vs baseline: 3.5775x; 1.0730x over previous
#include <cuda_runtime.h>
#include <cuda_bf16.h>
#include <cstdint>

// Problem constants
static constexpr int Bc = 2, Lc = 2048, Dc = 1024, Hc = 16, HDc = 64;
static constexpr int Mc = Bc * Lc;  // 4096
static constexpr float SCALE = 0.125f;

// ---------------------------------------------------------------------------
// __device__ scratch (allocation-free rule). All bf16 hi/lo pairs.
// ---------------------------------------------------------------------------
__device__ __nv_bfloat16 g_xh[Mc * Dc], g_xl[Mc * Dc];           // x
__device__ __nv_bfloat16 g_wh[3 * Dc * Dc], g_wl[3 * Dc * Dc];   // qkv_w
__device__ __nv_bfloat16 g_pwh[Dc * Dc], g_pwl[Dc * Dc];         // proj_w
__device__ __nv_bfloat16 g_qh[Mc * Dc], g_ql[Mc * Dc];           // [B,H,L,Hd] (pre-scaled)
__device__ __nv_bfloat16 g_kh[Mc * Dc], g_kl[Mc * Dc];
__device__ __nv_bfloat16 g_vh[Mc * Dc], g_vl[Mc * Dc];
__device__ __nv_bfloat16 g_ah[Mc * Dc], g_al[Mc * Dc];           // attn out [B,L,D]

// ---------------------------------------------------------------------------
// helpers
// ---------------------------------------------------------------------------
__device__ __forceinline__ uint32_t smem_u32(const void* p) {
  uint32_t a;
  asm("{ .reg .u64 t; cvta.to.shared.u64 t, %1; cvt.u32.u64 %0, t; }"
      : "=r"(a) : "l"(p));
  return a;
}

__device__ __forceinline__ void mma16816(float* c, const uint32_t* a,
                                         const uint32_t* b) {
  asm volatile(
      "mma.sync.aligned.m16n8k16.row.col.f32.bf16.bf16.f32 "
      "{%0,%1,%2,%3}, {%4,%5,%6,%7}, {%8,%9}, {%0,%1,%2,%3};"
      : "+f"(c[0]), "+f"(c[1]), "+f"(c[2]), "+f"(c[3])
      : "r"(a[0]), "r"(a[1]), "r"(a[2]), "r"(a[3]), "r"(b[0]), "r"(b[1]));
}

__device__ __forceinline__ void ldsm_x4(uint32_t* r, uint32_t a) {
  asm volatile("ldmatrix.sync.aligned.m8n8.x4.shared.b16 {%0,%1,%2,%3}, [%4];"
               : "=r"(r[0]), "=r"(r[1]), "=r"(r[2]), "=r"(r[3]) : "r"(a));
}
__device__ __forceinline__ void ldsm_x4_t(uint32_t* r, uint32_t a) {
  asm volatile(
      "ldmatrix.sync.aligned.m8n8.x4.trans.shared.b16 {%0,%1,%2,%3}, [%4];"
      : "=r"(r[0]), "=r"(r[1]), "=r"(r[2]), "=r"(r[3]) : "r"(a));
}

__device__ __forceinline__ void cpasync16(uint32_t sp, const void* gp) {
  asm volatile("cp.async.cg.shared.global [%0], [%1], 16;"
               :: "r"(sp), "l"(gp) : "memory");
}
__device__ __forceinline__ void cp_commit() {
  asm volatile("cp.async.commit_group;" ::: "memory");
}
__device__ __forceinline__ void cp_wait0() {
  asm volatile("cp.async.wait_group 0;" ::: "memory");
}
__device__ __forceinline__ void cp_wait1() {
  asm volatile("cp.async.wait_group 1;" ::: "memory");
}

// split two fp32 into packed bf16x2 hi + residual lo
__device__ __forceinline__ void split_pack(float x, float y, uint32_t& hi,
                                           uint32_t& lo) {
  __nv_bfloat16 hx = __float2bfloat16(x), hy = __float2bfloat16(y);
  __nv_bfloat162 hp(hx, hy);
  hi = *reinterpret_cast<uint32_t*>(&hp);
  __nv_bfloat162 lp(__float2bfloat16(x - __bfloat162float(hx)),
                    __float2bfloat16(y - __bfloat162float(hy)));
  lo = *reinterpret_cast<uint32_t*>(&lp);
}

// ---------------------------------------------------------------------------
// fp32 -> bf16 hi/lo conversion. which: 0=x, 1=qkv_w, 2=proj_w
// ---------------------------------------------------------------------------
__global__ __launch_bounds__(256) void convert_hilo(const float* __restrict__ src,
                                                    int which, int n4) {
  int i = blockIdx.x * 256 + threadIdx.x;
  if (i >= n4) return;
  __nv_bfloat16 *hi, *lo;
  if (which == 0)      { hi = g_xh;  lo = g_xl; }
  else if (which == 1) { hi = g_wh;  lo = g_wl; }
  else                 { hi = g_pwh; lo = g_pwl; }
  float4 v = ((const float4*)src)[i];
  uint32_t h0, l0, h1, l1;
  split_pack(v.x, v.y, h0, l0);
  split_pack(v.z, v.w, h1, l1);
  ((uint32_t*)hi)[2 * i] = h0; ((uint32_t*)hi)[2 * i + 1] = h1;
  ((uint32_t*)lo)[2 * i] = l0; ((uint32_t*)lo)[2 * i + 1] = l1;
}

// ---------------------------------------------------------------------------
// HMMA GEMM: C[m,n] = sum_k A[m,k]*W[n,k] + bias[n]   (K = 1024)
// MODE 0: A = x hi/lo,   W = qkv_w hi/lo -> bf16 hi/lo scatter into q/k/v
//         (q pre-scaled by SCALE)
// MODE 1: A = attn hi/lo, W = proj_w hi/lo -> fp32 out
// Block 128x128, 256 thr (8 warps: 4m x 2n, warp tile 32x64).
// K-chunks of 32, cp.async double-buffered, ONE barrier per chunk.
// B fragments via ldmatrix.x4 (two n-tiles per instruction). 3-pass hi/lo.
// ---------------------------------------------------------------------------
static constexpr int GROW = 80;             // 32 bf16 (64B) + 16B pad
static constexpr int GARR = 128 * GROW;     // 10240
static constexpr int GSTAGE = 4 * GARR;     // 40960
static constexpr int GEMM_SMEM = 2 * GSTAGE;  // 81920

template <int MODE>
__global__ __launch_bounds__(256, 2) void hmma_gemm(const float* __restrict__ bias,
                                                    float* __restrict__ out) {
  extern __shared__ char smraw[];
  const int tid = threadIdx.x, lane = tid & 31, wid = tid >> 5;
  const int wm = wid & 3, wn = wid >> 2;
  const int n0 = blockIdx.x * 128, m0 = blockIdx.y * 128;
  const uint32_t sbase = smem_u32(smraw);

  const __nv_bfloat16* A0 = (MODE == 0) ? g_xh : g_ah;
  const __nv_bfloat16* A1 = (MODE == 0) ? g_xl : g_al;
  const __nv_bfloat16* B0 = (MODE == 0) ? g_wh : g_pwh;
  const __nv_bfloat16* B1 = (MODE == 0) ? g_wl : g_pwl;

  auto issue = [&](int kc) {
    const int k0 = kc * 32;
    const uint32_t sb = sbase + (kc & 1) * GSTAGE;
#pragma unroll
    for (int arr = 0; arr < 4; arr++) {
      const __nv_bfloat16* g =
          (arr == 0) ? A0 : (arr == 1) ? A1 : (arr == 2) ? B0 : B1;
      const int r0 = (arr < 2) ? m0 : n0;
      const uint32_t dbase = sb + arr * GARR;
#pragma unroll
      for (int it = 0; it < 2; it++) {
        int u = tid + it * 256;       // 0..511
        int r = u >> 2, c4 = u & 3;   // row, 16B chunk within 64B row
        cpasync16(dbase + r * GROW + c4 * 16,
                  g + (size_t)(r0 + r) * 1024 + k0 + c4 * 8);
      }
    }
    cp_commit();
  };

  float c[2][8][4];
#pragma unroll
  for (int mt = 0; mt < 2; mt++)
#pragma unroll
    for (int nt = 0; nt < 8; nt++)
#pragma unroll
      for (int e = 0; e < 4; e++) c[mt][nt][e] = 0.f;

  issue(0);
  for (int kc = 0; kc < 32; kc++) {
    cp_wait0();
    __syncthreads();
    if (kc + 1 < 32) issue(kc + 1);
    const uint32_t sb = sbase + (kc & 1) * GSTAGE;
#pragma unroll
    for (int ks = 0; ks < 2; ks++) {
      const int kk = ks * 16;
      uint32_t ah[2][4], al[2][4];
#pragma unroll
      for (int mt = 0; mt < 2; mt++) {
        int row = wm * 32 + mt * 16 + (lane & 15);
        uint32_t a = sb + row * GROW + (kk + (lane >> 4) * 8) * 2;
        ldsm_x4(ah[mt], a);
        ldsm_x4(al[mt], a + GARR);
      }
#pragma unroll
      for (int ntp = 0; ntp < 4; ntp++) {
        int row = wn * 64 + ntp * 16 + (lane & 7) + ((lane >> 4) & 1) * 8;
        uint32_t a = sb + 2 * GARR + row * GROW +
                     (kk + ((lane >> 3) & 1) * 8) * 2;
        uint32_t bh4[4], bl4[4];
        ldsm_x4(bh4, a);
        ldsm_x4(bl4, a + GARR);
#pragma unroll
        for (int e = 0; e < 2; e++) {
          const int nt = ntp * 2 + e;
          const uint32_t* bh = bh4 + 2 * e;
          const uint32_t* bl = bl4 + 2 * e;
#pragma unroll
          for (int mt = 0; mt < 2; mt++) {
            mma16816(c[mt][nt], ah[mt], bh);
            mma16816(c[mt][nt], ah[mt], bl);
            mma16816(c[mt][nt], al[mt], bh);
          }
        }
      }
    }
  }

  // Epilogue
#pragma unroll
  for (int mt = 0; mt < 2; mt++) {
#pragma unroll
    for (int half = 0; half < 2; half++) {
      const int m = m0 + wm * 32 + mt * 16 + (lane >> 2) + half * 8;
#pragma unroll
      for (int nt = 0; nt < 8; nt++) {
        const int n = n0 + wn * 64 + nt * 8 + (lane & 3) * 2;
        float v0 = c[mt][nt][half * 2 + 0] + bias[n];
        float v1 = c[mt][nt][half * 2 + 1] + bias[n + 1];
        if (MODE == 0) {
          const int three = n >> 10;
          const int h = (n & 1023) >> 6;
          const int d = n & 63;
          const int b = m >> 11, l = m & 2047;
          size_t idx = ((size_t)((b * 16 + h) * 2048 + l)) * 64 + d;
          if (three == 0) { v0 *= SCALE; v1 *= SCALE; }  // fold softmax scale
          uint32_t hv, lv;
          split_pack(v0, v1, hv, lv);
          __nv_bfloat16 *ph, *pl;
          if (three == 0)      { ph = g_qh; pl = g_ql; }
          else if (three == 1) { ph = g_kh; pl = g_kl; }
          else                 { ph = g_vh; pl = g_vl; }
          *(uint32_t*)(ph + idx) = hv;
          *(uint32_t*)(pl + idx) = lv;
        } else {
          *(float2*)(out + (size_t)m * 1024 + n) = make_float2(v0, v1);
        }
      }
    }
  }
}

// ---------------------------------------------------------------------------
// Flash attention on HMMA. Block = (q-tile 128, bh), 256 thr (8 warps).
// Warp owns 16 q rows. QK^T 3-pass hi/lo (Qh frags hoisted); softmax fp32;
// P.V 3-pass. K/V cp.async double-buffered, ONE barrier per kt.
// SMEM: Qh|Ql (128x144) + 2 stages x (Kh|Kl|Vh|Vl, each 64x144).
// ---------------------------------------------------------------------------
static constexpr int AROW = 144;
static constexpr int AKV = 64 * AROW;               // 9216
static constexpr int AQ = 128 * AROW;               // 18432
static constexpr int ASTAGE = 4 * AKV;              // 36864
static constexpr int ATTN_SMEM = 2 * AQ + 2 * ASTAGE;  // 110592

__global__ __launch_bounds__(256, 2) void attn_mma() {
  extern __shared__ char smraw[];
  const int tid = threadIdx.x, lane = tid & 31, wid = tid >> 5;
  const int q0 = blockIdx.x * 128, bh = blockIdx.y;
  const uint32_t sb = smem_u32(smraw);
  const uint32_t kvbase = sb + 2 * AQ;

  // Load Q hi/lo (128 x 64 bf16 each) via cp.async
  const size_t qoff = ((size_t)bh * 2048 + q0) * 64;
#pragma unroll
  for (int it = 0; it < 4; it++) {
    int u = tid + it * 256;          // 0..1023
    int r = u >> 3, c8 = u & 7;
    uint32_t so = r * AROW + c8 * 16;
    size_t go = qoff + r * 64 + c8 * 8;
    cpasync16(sb + so, g_qh + go);
    cpasync16(sb + AQ + so, g_ql + go);
  }
  cp_commit();

  auto issue_kv = [&](int kt) {
    const uint32_t st = kvbase + (kt & 1) * ASTAGE;
    const size_t koff = ((size_t)bh * 2048 + kt * 64) * 64;
#pragma unroll
    for (int it = 0; it < 2; it++) {
      int u = tid + it * 256;        // 0..511
      int r = u >> 3, c8 = u & 7;
      uint32_t so = r * AROW + c8 * 16;
      size_t go = koff + r * 64 + c8 * 8;
      cpasync16(st + so,            g_kh + go);
      cpasync16(st + AKV + so,      g_kl + go);
      cpasync16(st + 2 * AKV + so,  g_vh + go);
      cpasync16(st + 3 * AKV + so,  g_vl + go);
    }
    cp_commit();
  };

  issue_kv(0);

  // Hoist Qh fragments (loop-invariant): wait for Q (allow kv0 in flight)
  cp_wait1();
  __syncthreads();
  uint32_t qh[4][4];
#pragma unroll
  for (int ks = 0; ks < 4; ks++) {
    int row = wid * 16 + (lane & 15);
    uint32_t a = sb + row * AROW + (ks * 16 + (lane >> 4) * 8) * 2;
    ldsm_x4(qh[ks], a);
  }

  float o[8][4];
  float m_s[2] = {-1e30f, -1e30f}, l_s[2] = {0.f, 0.f};
#pragma unroll
  for (int nt = 0; nt < 8; nt++)
#pragma unroll
    for (int e = 0; e < 4; e++) o[nt][e] = 0.f;

  for (int kt = 0; kt < 32; kt++) {
    cp_wait0();
    __syncthreads();
    if (kt + 1 < 32) issue_kv(kt + 1);
    const uint32_t st = kvbase + (kt & 1) * ASTAGE;

    // S = Q K^T (64 keys), 3-pass
    float s[8][4];
#pragma unroll
    for (int nt = 0; nt < 8; nt++)
#pragma unroll
      for (int e = 0; e < 4; e++) s[nt][e] = 0.f;

#pragma unroll
    for (int ks = 0; ks < 4; ks++) {
      const int kk = ks * 16;
      uint32_t ql[4];
      {
        int row = wid * 16 + (lane & 15);
        uint32_t a = sb + AQ + row * AROW + (kk + (lane >> 4) * 8) * 2;
        ldsm_x4(ql, a);
      }
#pragma unroll
      for (int ntp = 0; ntp < 4; ntp++) {
        int row = ntp * 16 + (lane & 7) + ((lane >> 4) & 1) * 8;
        uint32_t a = st + row * AROW + (kk + ((lane >> 3) & 1) * 8) * 2;
        uint32_t kh4[4], kl4[4];
        ldsm_x4(kh4, a);
        ldsm_x4(kl4, a + AKV);
#pragma unroll
        for (int e = 0; e < 2; e++) {
          const int nt = ntp * 2 + e;
          const uint32_t* bh = kh4 + 2 * e;
          const uint32_t* bl = kl4 + 2 * e;
          mma16816(s[nt], qh[ks], bh);
          mma16816(s[nt], qh[ks], bl);
          mma16816(s[nt], ql, bh);
        }
      }
    }

    // Online softmax (rows r=lane/4 and r+8; quad reduce over lanes xor1,xor2)
    // (Q pre-scaled by SCALE in the QKV epilogue)
#pragma unroll
    for (int half = 0; half < 2; half++) {
      float mx = -1e30f;
#pragma unroll
      for (int nt = 0; nt < 8; nt++)
        mx = fmaxf(mx, fmaxf(s[nt][half * 2], s[nt][half * 2 + 1]));
      mx = fmaxf(mx, __shfl_xor_sync(0xffffffffu, mx, 1));
      mx = fmaxf(mx, __shfl_xor_sync(0xffffffffu, mx, 2));
      float mn = fmaxf(m_s[half], mx);
      float alpha = __expf(m_s[half] - mn);
      float ps = 0.f;
#pragma unroll
      for (int nt = 0; nt < 8; nt++) {
        float p0 = __expf(s[nt][half * 2] - mn);
        float p1 = __expf(s[nt][half * 2 + 1] - mn);
        s[nt][half * 2] = p0;
        s[nt][half * 2 + 1] = p1;
        ps += p0 + p1;
      }
      ps += __shfl_xor_sync(0xffffffffu, ps, 1);
      ps += __shfl_xor_sync(0xffffffffu, ps, 2);
      l_s[half] = l_s[half] * alpha + ps;
      m_s[half] = mn;
#pragma unroll
      for (int nt = 0; nt < 8; nt++) {
        o[nt][half * 2]     *= alpha;
        o[nt][half * 2 + 1] *= alpha;
      }
    }

    // O += P V, 3-pass (P hi/lo in regs, V hi/lo via ldmatrix.x4.trans)
#pragma unroll
    for (int ks = 0; ks < 4; ks++) {
      const int t0 = 2 * ks, t1 = 2 * ks + 1;
      uint32_t pah[4], pal[4];
      split_pack(s[t0][0], s[t0][1], pah[0], pal[0]);
      split_pack(s[t0][2], s[t0][3], pah[1], pal[1]);
      split_pack(s[t1][0], s[t1][1], pah[2], pal[2]);
      split_pack(s[t1][2], s[t1][3], pah[3], pal[3]);
      int row = ks * 16 + (lane & 7) + ((lane >> 3) & 1) * 8;
#pragma unroll
      for (int ntp = 0; ntp < 4; ntp++) {
        uint32_t a = st + 2 * AKV + row * AROW +
                     (ntp * 2 + ((lane >> 4) & 1)) * 16;
        uint32_t vh4[4], vl4[4];
        ldsm_x4_t(vh4, a);
        ldsm_x4_t(vl4, a + AKV);
#pragma unroll
        for (int e = 0; e < 2; e++) {
          const int nt = ntp * 2 + e;
          const uint32_t* bvh = vh4 + 2 * e;
          const uint32_t* bvl = vl4 + 2 * e;
          mma16816(o[nt], pah, bvh);
          mma16816(o[nt], pal, bvh);
          mma16816(o[nt], pah, bvl);
        }
      }
    }
  }

  // Epilogue: normalize, split hi/lo, write [B,L,D]
  const int b = bh >> 4, h = bh & 15;
#pragma unroll
  for (int half = 0; half < 2; half++) {
    const int row = q0 + wid * 16 + (lane >> 2) + half * 8;
    const float inv = 1.0f / l_s[half];
    const size_t base = ((size_t)(b * 2048 + row)) * 1024 + h * 64;
#pragma unroll
    for (int nt = 0; nt < 8; nt++) {
      const int d = nt * 8 + (lane & 3) * 2;
      float v0 = o[nt][half * 2] * inv;
      float v1 = o[nt][half * 2 + 1] * inv;
      uint32_t hv, lv;
      split_pack(v0, v1, hv, lv);
      *(uint32_t*)(g_ah + base + d) = hv;
      *(uint32_t*)(g_al + base + d) = lv;
    }
  }
}

// ---------------------------------------------------------------------------
extern "C" void kernel_launch(void* const* d_in, const int* in_sizes, int n_in,
                              void* d_out, int out_size) {
  const float* x      = (const float*)d_in[0];
  const float* qkv_w  = (const float*)d_in[1];
  const float* qkv_b  = (const float*)d_in[2];
  const float* proj_w = (const float*)d_in[3];
  const float* proj_b = (const float*)d_in[4];
  float* out = (float*)d_out;

  cudaFuncSetAttribute((const void*)hmma_gemm<0>,
                       cudaFuncAttributeMaxDynamicSharedMemorySize, GEMM_SMEM);
  cudaFuncSetAttribute((const void*)hmma_gemm<1>,
                       cudaFuncAttributeMaxDynamicSharedMemorySize, GEMM_SMEM);
  cudaFuncSetAttribute((const void*)attn_mma,
                       cudaFuncAttributeMaxDynamicSharedMemorySize, ATTN_SMEM);

  convert_hilo<<<Mc * Dc / 4 / 256, 256>>>(x, 0, Mc * Dc / 4);
  convert_hilo<<<3 * Dc * Dc / 4 / 256, 256>>>(qkv_w, 1, 3 * Dc * Dc / 4);
  convert_hilo<<<Dc * Dc / 4 / 256, 256>>>(proj_w, 2, Dc * Dc / 4);

  hmma_gemm<0><<<dim3(24, 32), 256, GEMM_SMEM>>>(qkv_b, nullptr);
  attn_mma<<<dim3(16, 32), 256, ATTN_SMEM>>>();
  hmma_gemm<1><<<dim3(8, 32), 256, GEMM_SMEM>>>(proj_b, out);
}

// round 7
// speedup vs baseline: 8.6592x; 2.4204x over previous
#include <cuda_runtime.h>
#include <cuda_fp16.h>
#include <cstdint>

// Problem constants
static constexpr int Bc = 2, Lc = 2048, Dc = 1024, Hc = 16, HDc = 64;
static constexpr int Mc = Bc * Lc;  // 4096
static constexpr float SCALE = 0.125f;

// ---------------------------------------------------------------------------
// __device__ scratch (allocation-free rule). Single fp16 copies.
// ---------------------------------------------------------------------------
__device__ __half g_x16[Mc * Dc];          // x
__device__ __half g_w16[3 * Dc * Dc];      // qkv_w
__device__ __half g_pw16[Dc * Dc];         // proj_w
__device__ __half g_q16[Mc * Dc];          // [B,H,L,Hd] (pre-scaled by SCALE)
__device__ __half g_k16[Mc * Dc];
__device__ __half g_v16[Mc * Dc];
__device__ __half g_a16[Mc * Dc];          // attn out [B,L,D]

// ---------------------------------------------------------------------------
// helpers
// ---------------------------------------------------------------------------
__device__ __forceinline__ uint32_t smem_u32(const void* p) {
  uint32_t a;
  asm("{ .reg .u64 t; cvta.to.shared.u64 t, %1; cvt.u32.u64 %0, t; }"
      : "=r"(a) : "l"(p));
  return a;
}

__device__ __forceinline__ void mma16816(float* c, const uint32_t* a,
                                         const uint32_t* b) {
  asm volatile(
      "mma.sync.aligned.m16n8k16.row.col.f32.f16.f16.f32 "
      "{%0,%1,%2,%3}, {%4,%5,%6,%7}, {%8,%9}, {%0,%1,%2,%3};"
      : "+f"(c[0]), "+f"(c[1]), "+f"(c[2]), "+f"(c[3])
      : "r"(a[0]), "r"(a[1]), "r"(a[2]), "r"(a[3]), "r"(b[0]), "r"(b[1]));
}

__device__ __forceinline__ void ldsm_x4(uint32_t* r, uint32_t a) {
  asm volatile("ldmatrix.sync.aligned.m8n8.x4.shared.b16 {%0,%1,%2,%3}, [%4];"
               : "=r"(r[0]), "=r"(r[1]), "=r"(r[2]), "=r"(r[3]) : "r"(a));
}
__device__ __forceinline__ void ldsm_x4_t(uint32_t* r, uint32_t a) {
  asm volatile(
      "ldmatrix.sync.aligned.m8n8.x4.trans.shared.b16 {%0,%1,%2,%3}, [%4];"
      : "=r"(r[0]), "=r"(r[1]), "=r"(r[2]), "=r"(r[3]) : "r"(a));
}

__device__ __forceinline__ void cpasync16(uint32_t sp, const void* gp) {
  asm volatile("cp.async.cg.shared.global [%0], [%1], 16;"
               :: "r"(sp), "l"(gp) : "memory");
}
__device__ __forceinline__ void cp_commit() {
  asm volatile("cp.async.commit_group;" ::: "memory");
}
__device__ __forceinline__ void cp_wait0() {
  asm volatile("cp.async.wait_group 0;" ::: "memory");
}
__device__ __forceinline__ void cp_wait1() {
  asm volatile("cp.async.wait_group 1;" ::: "memory");
}

__device__ __forceinline__ uint32_t pack_half2(float x, float y) {
  __half2 h = __floats2half2_rn(x, y);
  return *reinterpret_cast<uint32_t*>(&h);
}

// ---------------------------------------------------------------------------
// fp32 -> fp16 conversion. which: 0=x, 1=qkv_w, 2=proj_w
// ---------------------------------------------------------------------------
__global__ __launch_bounds__(256) void convert_f16(const float* __restrict__ src,
                                                   int which, int n4) {
  int i = blockIdx.x * 256 + threadIdx.x;
  if (i >= n4) return;
  __half* dst;
  if (which == 0)      dst = g_x16;
  else if (which == 1) dst = g_w16;
  else                 dst = g_pw16;
  float4 v = ((const float4*)src)[i];
  ((uint32_t*)dst)[2 * i]     = pack_half2(v.x, v.y);
  ((uint32_t*)dst)[2 * i + 1] = pack_half2(v.z, v.w);
}

// ---------------------------------------------------------------------------
// HMMA GEMM (fp16 single pass): C[m,n] = sum_k A[m,k]*W[n,k] + bias[n], K=1024
// MODE 0: A = x16, W = w16 -> fp16 scatter into q/k/v (q pre-scaled by SCALE)
// MODE 1: A = a16, W = pw16 -> fp32 out
// Block 128x128, 256 thr (8 warps: 4m x 2n, warp tile 32x64).
// K-chunks of 64, cp.async double-buffered, one barrier per chunk.
// SMEM rows 128B data + 16B pad = 144B (conflict-free ldmatrix).
// ---------------------------------------------------------------------------
static constexpr int GROW = 144;
static constexpr int GARR = 128 * GROW;       // 18432
static constexpr int GSTAGE = 2 * GARR;       // 36864 (A | B)
static constexpr int GEMM_SMEM = 2 * GSTAGE;  // 73728

template <int MODE>
__global__ __launch_bounds__(256, 2) void hmma_gemm(const float* __restrict__ bias,
                                                    float* __restrict__ out) {
  extern __shared__ char smraw[];
  const int tid = threadIdx.x, lane = tid & 31, wid = tid >> 5;
  const int wm = wid & 3, wn = wid >> 2;
  const int n0 = blockIdx.x * 128, m0 = blockIdx.y * 128;
  const uint32_t sbase = smem_u32(smraw);

  const __half* A = (MODE == 0) ? g_x16 : g_a16;
  const __half* B = (MODE == 0) ? g_w16 : g_pw16;

  auto issue = [&](int kc) {
    const int k0 = kc * 64;
    const uint32_t sb = sbase + (kc & 1) * GSTAGE;
#pragma unroll
    for (int arr = 0; arr < 2; arr++) {
      const __half* g = (arr == 0) ? A : B;
      const int r0 = (arr == 0) ? m0 : n0;
      const uint32_t dbase = sb + arr * GARR;
#pragma unroll
      for (int it = 0; it < 4; it++) {
        int u = tid + it * 256;       // 0..1023
        int r = u >> 3, c8 = u & 7;   // row, 16B chunk within 128B row
        cpasync16(dbase + r * GROW + c8 * 16,
                  g + (size_t)(r0 + r) * 1024 + k0 + c8 * 8);
      }
    }
    cp_commit();
  };

  float c[2][8][4];
#pragma unroll
  for (int mt = 0; mt < 2; mt++)
#pragma unroll
    for (int nt = 0; nt < 8; nt++)
#pragma unroll
      for (int e = 0; e < 4; e++) c[mt][nt][e] = 0.f;

  issue(0);
  for (int kc = 0; kc < 16; kc++) {
    cp_wait0();
    __syncthreads();
    if (kc + 1 < 16) issue(kc + 1);
    const uint32_t sb = sbase + (kc & 1) * GSTAGE;
#pragma unroll
    for (int ks = 0; ks < 4; ks++) {
      const int kk = ks * 16;
      uint32_t af[2][4];
#pragma unroll
      for (int mt = 0; mt < 2; mt++) {
        int row = wm * 32 + mt * 16 + (lane & 15);
        ldsm_x4(af[mt], sb + row * GROW + (kk + (lane >> 4) * 8) * 2);
      }
#pragma unroll
      for (int ntp = 0; ntp < 4; ntp++) {
        int row = wn * 64 + ntp * 16 + (lane & 7) + ((lane >> 4) & 1) * 8;
        uint32_t bf4[4];
        ldsm_x4(bf4, sb + GARR + row * GROW +
                         (kk + ((lane >> 3) & 1) * 8) * 2);
#pragma unroll
        for (int e = 0; e < 2; e++) {
          const int nt = ntp * 2 + e;
#pragma unroll
          for (int mt = 0; mt < 2; mt++)
            mma16816(c[mt][nt], af[mt], bf4 + 2 * e);
        }
      }
    }
  }

  // Epilogue
#pragma unroll
  for (int mt = 0; mt < 2; mt++) {
#pragma unroll
    for (int half = 0; half < 2; half++) {
      const int m = m0 + wm * 32 + mt * 16 + (lane >> 2) + half * 8;
#pragma unroll
      for (int nt = 0; nt < 8; nt++) {
        const int n = n0 + wn * 64 + nt * 8 + (lane & 3) * 2;
        float v0 = c[mt][nt][half * 2 + 0] + bias[n];
        float v1 = c[mt][nt][half * 2 + 1] + bias[n + 1];
        if (MODE == 0) {
          const int three = n >> 10;
          const int h = (n & 1023) >> 6;
          const int d = n & 63;
          const int b = m >> 11, l = m & 2047;
          size_t idx = ((size_t)((b * 16 + h) * 2048 + l)) * 64 + d;
          if (three == 0) { v0 *= SCALE; v1 *= SCALE; }  // fold softmax scale
          __half* p = (three == 0) ? g_q16 : (three == 1) ? g_k16 : g_v16;
          *(uint32_t*)(p + idx) = pack_half2(v0, v1);
        } else {
          *(float2*)(out + (size_t)m * 1024 + n) = make_float2(v0, v1);
        }
      }
    }
  }
}

// ---------------------------------------------------------------------------
// Flash attention on fp16 HMMA. Block = (q-tile 128, bh), 256 thr (8 warps).
// Warp owns 16 q rows. Q fragments hoisted; softmax fp32 in fragments;
// P packed to fp16 in regs; V via ldmatrix.x4.trans.
// K/V cp.async double-buffered, one barrier per kt.
// SMEM: Q (128x144) + 2 stages x (K|V, each 64x144).
// ---------------------------------------------------------------------------
static constexpr int AROW = 144;
static constexpr int AKV = 64 * AROW;               // 9216
static constexpr int AQ = 128 * AROW;               // 18432
static constexpr int ASTAGE = 2 * AKV;              // 18432
static constexpr int ATTN_SMEM = AQ + 2 * ASTAGE;   // 55296

__global__ __launch_bounds__(256, 2) void attn_mma() {
  extern __shared__ char smraw[];
  const int tid = threadIdx.x, lane = tid & 31, wid = tid >> 5;
  const int q0 = blockIdx.x * 128, bh = blockIdx.y;
  const uint32_t sb = smem_u32(smraw);
  const uint32_t kvbase = sb + AQ;

  // Load Q (128 x 64 fp16) via cp.async
  const size_t qoff = ((size_t)bh * 2048 + q0) * 64;
#pragma unroll
  for (int it = 0; it < 4; it++) {
    int u = tid + it * 256;          // 0..1023
    int r = u >> 3, c8 = u & 7;
    cpasync16(sb + r * AROW + c8 * 16, g_q16 + qoff + r * 64 + c8 * 8);
  }
  cp_commit();

  auto issue_kv = [&](int kt) {
    const uint32_t st = kvbase + (kt & 1) * ASTAGE;
    const size_t koff = ((size_t)bh * 2048 + kt * 64) * 64;
#pragma unroll
    for (int it = 0; it < 2; it++) {
      int u = tid + it * 256;        // 0..511
      int r = u >> 3, c8 = u & 7;
      uint32_t so = r * AROW + c8 * 16;
      size_t go = koff + r * 64 + c8 * 8;
      cpasync16(st + so,       g_k16 + go);
      cpasync16(st + AKV + so, g_v16 + go);
    }
    cp_commit();
  };

  issue_kv(0);

  // Hoist Q fragments (loop-invariant): wait for Q (kv0 still in flight)
  cp_wait1();
  __syncthreads();
  uint32_t qf[4][4];
#pragma unroll
  for (int ks = 0; ks < 4; ks++) {
    int row = wid * 16 + (lane & 15);
    ldsm_x4(qf[ks], sb + row * AROW + (ks * 16 + (lane >> 4) * 8) * 2);
  }

  float o[8][4];
  float m_s[2] = {-1e30f, -1e30f}, l_s[2] = {0.f, 0.f};
#pragma unroll
  for (int nt = 0; nt < 8; nt++)
#pragma unroll
    for (int e = 0; e < 4; e++) o[nt][e] = 0.f;

  for (int kt = 0; kt < 32; kt++) {
    cp_wait0();
    __syncthreads();
    if (kt + 1 < 32) issue_kv(kt + 1);
    const uint32_t st = kvbase + (kt & 1) * ASTAGE;

    // S = Q K^T (64 keys)
    float s[8][4];
#pragma unroll
    for (int nt = 0; nt < 8; nt++)
#pragma unroll
      for (int e = 0; e < 4; e++) s[nt][e] = 0.f;

#pragma unroll
    for (int ks = 0; ks < 4; ks++) {
      const int kk = ks * 16;
#pragma unroll
      for (int ntp = 0; ntp < 4; ntp++) {
        int row = ntp * 16 + (lane & 7) + ((lane >> 4) & 1) * 8;
        uint32_t kf4[4];
        ldsm_x4(kf4, st + row * AROW + (kk + ((lane >> 3) & 1) * 8) * 2);
#pragma unroll
        for (int e = 0; e < 2; e++)
          mma16816(s[ntp * 2 + e], qf[ks], kf4 + 2 * e);
      }
    }

    // Online softmax (rows r=lane/4 and r+8; quad reduce over lanes xor1,xor2)
    // (Q pre-scaled by SCALE in the QKV epilogue)
#pragma unroll
    for (int half = 0; half < 2; half++) {
      float mx = -1e30f;
#pragma unroll
      for (int nt = 0; nt < 8; nt++)
        mx = fmaxf(mx, fmaxf(s[nt][half * 2], s[nt][half * 2 + 1]));
      mx = fmaxf(mx, __shfl_xor_sync(0xffffffffu, mx, 1));
      mx = fmaxf(mx, __shfl_xor_sync(0xffffffffu, mx, 2));
      float mn = fmaxf(m_s[half], mx);
      float alpha = __expf(m_s[half] - mn);
      float ps = 0.f;
#pragma unroll
      for (int nt = 0; nt < 8; nt++) {
        float p0 = __expf(s[nt][half * 2] - mn);
        float p1 = __expf(s[nt][half * 2 + 1] - mn);
        s[nt][half * 2] = p0;
        s[nt][half * 2 + 1] = p1;
        ps += p0 + p1;
      }
      ps += __shfl_xor_sync(0xffffffffu, ps, 1);
      ps += __shfl_xor_sync(0xffffffffu, ps, 2);
      l_s[half] = l_s[half] * alpha + ps;
      m_s[half] = mn;
#pragma unroll
      for (int nt = 0; nt < 8; nt++) {
        o[nt][half * 2]     *= alpha;
        o[nt][half * 2 + 1] *= alpha;
      }
    }

    // O += P V (P packed fp16 in regs, V via ldmatrix.x4.trans)
#pragma unroll
    for (int ks = 0; ks < 4; ks++) {
      const int t0 = 2 * ks, t1 = 2 * ks + 1;
      uint32_t pa[4];
      pa[0] = pack_half2(s[t0][0], s[t0][1]);
      pa[1] = pack_half2(s[t0][2], s[t0][3]);
      pa[2] = pack_half2(s[t1][0], s[t1][1]);
      pa[3] = pack_half2(s[t1][2], s[t1][3]);
      int row = ks * 16 + (lane & 7) + ((lane >> 3) & 1) * 8;
#pragma unroll
      for (int ntp = 0; ntp < 4; ntp++) {
        uint32_t vf4[4];
        ldsm_x4_t(vf4, st + AKV + row * AROW +
                           (ntp * 2 + ((lane >> 4) & 1)) * 16);
#pragma unroll
        for (int e = 0; e < 2; e++)
          mma16816(o[ntp * 2 + e], pa, vf4 + 2 * e);
      }
    }
  }

  // Epilogue: normalize, write fp16 [B,L,D]
  const int b = bh >> 4, h = bh & 15;
#pragma unroll
  for (int half = 0; half < 2; half++) {
    const int row = q0 + wid * 16 + (lane >> 2) + half * 8;
    const float inv = 1.0f / l_s[half];
    const size_t base = ((size_t)(b * 2048 + row)) * 1024 + h * 64;
#pragma unroll
    for (int nt = 0; nt < 8; nt++) {
      const int d = nt * 8 + (lane & 3) * 2;
      *(uint32_t*)(g_a16 + base + d) =
          pack_half2(o[nt][half * 2] * inv, o[nt][half * 2 + 1] * inv);
    }
  }
}

// ---------------------------------------------------------------------------
extern "C" void kernel_launch(void* const* d_in, const int* in_sizes, int n_in,
                              void* d_out, int out_size) {
  const float* x      = (const float*)d_in[0];
  const float* qkv_w  = (const float*)d_in[1];
  const float* qkv_b  = (const float*)d_in[2];
  const float* proj_w = (const float*)d_in[3];
  const float* proj_b = (const float*)d_in[4];
  float* out = (float*)d_out;

  cudaFuncSetAttribute((const void*)hmma_gemm<0>,
                       cudaFuncAttributeMaxDynamicSharedMemorySize, GEMM_SMEM);
  cudaFuncSetAttribute((const void*)hmma_gemm<1>,
                       cudaFuncAttributeMaxDynamicSharedMemorySize, GEMM_SMEM);
  cudaFuncSetAttribute((const void*)attn_mma,
                       cudaFuncAttributeMaxDynamicSharedMemorySize, ATTN_SMEM);

  convert_f16<<<Mc * Dc / 4 / 256, 256>>>(x, 0, Mc * Dc / 4);
  convert_f16<<<3 * Dc * Dc / 4 / 256, 256>>>(qkv_w, 1, 3 * Dc * Dc / 4);
  convert_f16<<<Dc * Dc / 4 / 256, 256>>>(proj_w, 2, Dc * Dc / 4);

  hmma_gemm<0><<<dim3(24, 32), 256, GEMM_SMEM>>>(qkv_b, nullptr);
  attn_mma<<<dim3(16, 32), 256, ATTN_SMEM>>>();
  hmma_gemm<1><<<dim3(8, 32), 256, GEMM_SMEM>>>(proj_b, out);
}

// round 8
// speedup vs baseline: 9.3214x; 1.0765x over previous
#include <cuda_runtime.h>
#include <cuda_fp16.h>
#include <cstdint>

// Problem constants
static constexpr int Bc = 2, Lc = 2048, Dc = 1024, Hc = 16, HDc = 64;
static constexpr int Mc = Bc * Lc;  // 4096
static constexpr float SCALE = 0.125f;

// ---------------------------------------------------------------------------
// __device__ scratch (allocation-free rule). Single fp16 copies.
// ---------------------------------------------------------------------------
__device__ __half g_x16[Mc * Dc];          // x
__device__ __half g_w16[3 * Dc * Dc];      // qkv_w
__device__ __half g_pw16[Dc * Dc];         // proj_w
__device__ __half g_q16[Mc * Dc];          // [B,H,L,Hd] (pre-scaled by SCALE)
__device__ __half g_k16[Mc * Dc];
__device__ __half g_v16[Mc * Dc];
__device__ __half g_a16[Mc * Dc];          // attn out [B,L,D]

// ---------------------------------------------------------------------------
// helpers
// ---------------------------------------------------------------------------
__device__ __forceinline__ uint32_t smem_u32(const void* p) {
  uint32_t a;
  asm("{ .reg .u64 t; cvta.to.shared.u64 t, %1; cvt.u32.u64 %0, t; }"
      : "=r"(a) : "l"(p));
  return a;
}

__device__ __forceinline__ void mma16816(float* c, const uint32_t* a,
                                         const uint32_t* b) {
  asm volatile(
      "mma.sync.aligned.m16n8k16.row.col.f32.f16.f16.f32 "
      "{%0,%1,%2,%3}, {%4,%5,%6,%7}, {%8,%9}, {%0,%1,%2,%3};"
      : "+f"(c[0]), "+f"(c[1]), "+f"(c[2]), "+f"(c[3])
      : "r"(a[0]), "r"(a[1]), "r"(a[2]), "r"(a[3]), "r"(b[0]), "r"(b[1]));
}

__device__ __forceinline__ void ldsm_x4(uint32_t* r, uint32_t a) {
  asm volatile("ldmatrix.sync.aligned.m8n8.x4.shared.b16 {%0,%1,%2,%3}, [%4];"
               : "=r"(r[0]), "=r"(r[1]), "=r"(r[2]), "=r"(r[3]) : "r"(a));
}
__device__ __forceinline__ void ldsm_x4_t(uint32_t* r, uint32_t a) {
  asm volatile(
      "ldmatrix.sync.aligned.m8n8.x4.trans.shared.b16 {%0,%1,%2,%3}, [%4];"
      : "=r"(r[0]), "=r"(r[1]), "=r"(r[2]), "=r"(r[3]) : "r"(a));
}

__device__ __forceinline__ void cpasync16(uint32_t sp, const void* gp) {
  asm volatile("cp.async.cg.shared.global [%0], [%1], 16;"
               :: "r"(sp), "l"(gp) : "memory");
}
__device__ __forceinline__ void cp_commit() {
  asm volatile("cp.async.commit_group;" ::: "memory");
}
__device__ __forceinline__ void cp_wait0() {
  asm volatile("cp.async.wait_group 0;" ::: "memory");
}
__device__ __forceinline__ void cp_wait1() {
  asm volatile("cp.async.wait_group 1;" ::: "memory");
}

__device__ __forceinline__ uint32_t pack_half2(float x, float y) {
  __half2 h = __floats2half2_rn(x, y);
  return *reinterpret_cast<uint32_t*>(&h);
}

// ---------------------------------------------------------------------------
// Single fused fp32 -> fp16 conversion for x, qkv_w, proj_w
// ---------------------------------------------------------------------------
static constexpr int NXQ = Mc * Dc / 4;        // 1048576 quads
static constexpr int NWQ = 3 * Dc * Dc / 4;    // 786432
static constexpr int NPQ = Dc * Dc / 4;        // 262144
static constexpr int NALLQ = NXQ + NWQ + NPQ;  // 2097152

__global__ __launch_bounds__(256) void convert_all(
    const float* __restrict__ x, const float* __restrict__ w,
    const float* __restrict__ pw) {
  int i = blockIdx.x * 256 + threadIdx.x;
  if (i >= NALLQ) return;
  const float* src;
  __half* dst;
  int off;
  if (i < NXQ)            { src = x;  dst = g_x16;  off = i; }
  else if (i < NXQ + NWQ) { src = w;  dst = g_w16;  off = i - NXQ; }
  else                    { src = pw; dst = g_pw16; off = i - NXQ - NWQ; }
  float4 v = ((const float4*)src)[off];
  ((uint32_t*)dst)[2 * off]     = pack_half2(v.x, v.y);
  ((uint32_t*)dst)[2 * off + 1] = pack_half2(v.z, v.w);
}

// ---------------------------------------------------------------------------
// HMMA GEMM (fp16): C[m,n] = sum_k A[m,k]*W[n,k] + bias[n], K=1024
// MODE 0: A = x16, W = w16 -> fp16 scatter into q/k/v (q pre-scaled by SCALE)
// MODE 1: A = a16, W = pw16 -> fp32 out
// CTA tile 64x128, 128 thr (4 warps: 2m x 2n, warp tile 32x64). 4 CTAs/SM.
// K-chunks of 64, cp.async double-buffered, one barrier per chunk.
// SMEM rows 128B data + 16B pad = 144B.
// ---------------------------------------------------------------------------
static constexpr int GROW = 144;
static constexpr int GA = 64 * GROW;          // 9216  (A: 64 rows)
static constexpr int GB = 128 * GROW;         // 18432 (B: 128 rows)
static constexpr int GSTAGE = GA + GB;        // 27648
static constexpr int GEMM_SMEM = 2 * GSTAGE;  // 55296

template <int MODE>
__global__ __launch_bounds__(128, 4) void hmma_gemm(const float* __restrict__ bias,
                                                    float* __restrict__ out) {
  extern __shared__ char smraw[];
  const int tid = threadIdx.x, lane = tid & 31, wid = tid >> 5;
  const int wm = wid & 1, wn = wid >> 1;
  const int n0 = blockIdx.x * 128, m0 = blockIdx.y * 64;
  const uint32_t sbase = smem_u32(smraw);

  const __half* A = (MODE == 0) ? g_x16 : g_a16;
  const __half* B = (MODE == 0) ? g_w16 : g_pw16;

  auto issue = [&](int kc) {
    const int k0 = kc * 64;
    const uint32_t sb = sbase + (kc & 1) * GSTAGE;
#pragma unroll
    for (int it = 0; it < 4; it++) {     // A: 64 rows x 8 chunks = 512
      int u = tid + it * 128;
      int r = u >> 3, c8 = u & 7;
      cpasync16(sb + r * GROW + c8 * 16,
                A + (size_t)(m0 + r) * 1024 + k0 + c8 * 8);
    }
#pragma unroll
    for (int it = 0; it < 8; it++) {     // B: 128 rows x 8 chunks = 1024
      int u = tid + it * 128;
      int r = u >> 3, c8 = u & 7;
      cpasync16(sb + GA + r * GROW + c8 * 16,
                B + (size_t)(n0 + r) * 1024 + k0 + c8 * 8);
    }
    cp_commit();
  };

  float c[2][8][4];
#pragma unroll
  for (int mt = 0; mt < 2; mt++)
#pragma unroll
    for (int nt = 0; nt < 8; nt++)
#pragma unroll
      for (int e = 0; e < 4; e++) c[mt][nt][e] = 0.f;

  issue(0);
  for (int kc = 0; kc < 16; kc++) {
    cp_wait0();
    __syncthreads();
    if (kc + 1 < 16) issue(kc + 1);
    const uint32_t sb = sbase + (kc & 1) * GSTAGE;
#pragma unroll
    for (int ks = 0; ks < 4; ks++) {
      const int kk = ks * 16;
      uint32_t af[2][4];
#pragma unroll
      for (int mt = 0; mt < 2; mt++) {
        int row = wm * 32 + mt * 16 + (lane & 15);
        ldsm_x4(af[mt], sb + row * GROW + (kk + (lane >> 4) * 8) * 2);
      }
#pragma unroll
      for (int ntp = 0; ntp < 4; ntp++) {
        int row = wn * 64 + ntp * 16 + (lane & 7) + ((lane >> 4) & 1) * 8;
        uint32_t bf4[4];
        ldsm_x4(bf4, sb + GA + row * GROW +
                         (kk + ((lane >> 3) & 1) * 8) * 2);
#pragma unroll
        for (int e = 0; e < 2; e++) {
          const int nt = ntp * 2 + e;
#pragma unroll
          for (int mt = 0; mt < 2; mt++)
            mma16816(c[mt][nt], af[mt], bf4 + 2 * e);
        }
      }
    }
  }

  // Epilogue
#pragma unroll
  for (int mt = 0; mt < 2; mt++) {
#pragma unroll
    for (int half = 0; half < 2; half++) {
      const int m = m0 + wm * 32 + mt * 16 + (lane >> 2) + half * 8;
#pragma unroll
      for (int nt = 0; nt < 8; nt++) {
        const int n = n0 + wn * 64 + nt * 8 + (lane & 3) * 2;
        float v0 = c[mt][nt][half * 2 + 0] + bias[n];
        float v1 = c[mt][nt][half * 2 + 1] + bias[n + 1];
        if (MODE == 0) {
          const int three = n >> 10;
          const int h = (n & 1023) >> 6;
          const int d = n & 63;
          const int b = m >> 11, l = m & 2047;
          size_t idx = ((size_t)((b * 16 + h) * 2048 + l)) * 64 + d;
          if (three == 0) { v0 *= SCALE; v1 *= SCALE; }  // fold softmax scale
          __half* p = (three == 0) ? g_q16 : (three == 1) ? g_k16 : g_v16;
          *(uint32_t*)(p + idx) = pack_half2(v0, v1);
        } else {
          *(float2*)(out + (size_t)m * 1024 + n) = make_float2(v0, v1);
        }
      }
    }
  }
}

// ---------------------------------------------------------------------------
// Flash attention on fp16 HMMA. Block = (q-tile 64, bh), 128 thr (4 warps).
// 4 CTAs/SM. Warp owns 16 q rows. Q fragments hoisted; softmax fp32;
// P packed fp16 in regs; V via ldmatrix.x4.trans.
// K/V cp.async double-buffered, one barrier per kt.
// SMEM: Q (64x144) + 2 stages x (K|V, each 64x144) = 46080.
// ---------------------------------------------------------------------------
static constexpr int AROW = 144;
static constexpr int AKV = 64 * AROW;               // 9216
static constexpr int AQ = 64 * AROW;                // 9216
static constexpr int ASTAGE = 2 * AKV;              // 18432
static constexpr int ATTN_SMEM = AQ + 2 * ASTAGE;   // 46080

__global__ __launch_bounds__(128, 4) void attn_mma() {
  extern __shared__ char smraw[];
  const int tid = threadIdx.x, lane = tid & 31, wid = tid >> 5;
  const int q0 = blockIdx.x * 64, bh = blockIdx.y;
  const uint32_t sb = smem_u32(smraw);
  const uint32_t kvbase = sb + AQ;

  // Load Q (64 x 64 fp16) via cp.async
  const size_t qoff = ((size_t)bh * 2048 + q0) * 64;
#pragma unroll
  for (int it = 0; it < 4; it++) {
    int u = tid + it * 128;          // 0..511
    int r = u >> 3, c8 = u & 7;
    cpasync16(sb + r * AROW + c8 * 16, g_q16 + qoff + r * 64 + c8 * 8);
  }
  cp_commit();

  auto issue_kv = [&](int kt) {
    const uint32_t st = kvbase + (kt & 1) * ASTAGE;
    const size_t koff = ((size_t)bh * 2048 + kt * 64) * 64;
#pragma unroll
    for (int it = 0; it < 4; it++) {
      int u = tid + it * 128;        // 0..511
      int r = u >> 3, c8 = u & 7;
      uint32_t so = r * AROW + c8 * 16;
      size_t go = koff + r * 64 + c8 * 8;
      cpasync16(st + so,       g_k16 + go);
      cpasync16(st + AKV + so, g_v16 + go);
    }
    cp_commit();
  };

  issue_kv(0);

  // Hoist Q fragments (loop-invariant): wait for Q (kv0 still in flight)
  cp_wait1();
  __syncthreads();
  uint32_t qf[4][4];
#pragma unroll
  for (int ks = 0; ks < 4; ks++) {
    int row = wid * 16 + (lane & 15);
    ldsm_x4(qf[ks], sb + row * AROW + (ks * 16 + (lane >> 4) * 8) * 2);
  }

  float o[8][4];
  float m_s[2] = {-1e30f, -1e30f}, l_s[2] = {0.f, 0.f};
#pragma unroll
  for (int nt = 0; nt < 8; nt++)
#pragma unroll
    for (int e = 0; e < 4; e++) o[nt][e] = 0.f;

  for (int kt = 0; kt < 32; kt++) {
    cp_wait0();
    __syncthreads();
    if (kt + 1 < 32) issue_kv(kt + 1);
    const uint32_t st = kvbase + (kt & 1) * ASTAGE;

    // S = Q K^T (64 keys)
    float s[8][4];
#pragma unroll
    for (int nt = 0; nt < 8; nt++)
#pragma unroll
      for (int e = 0; e < 4; e++) s[nt][e] = 0.f;

#pragma unroll
    for (int ks = 0; ks < 4; ks++) {
      const int kk = ks * 16;
#pragma unroll
      for (int ntp = 0; ntp < 4; ntp++) {
        int row = ntp * 16 + (lane & 7) + ((lane >> 4) & 1) * 8;
        uint32_t kf4[4];
        ldsm_x4(kf4, st + row * AROW + (kk + ((lane >> 3) & 1) * 8) * 2);
#pragma unroll
        for (int e = 0; e < 2; e++)
          mma16816(s[ntp * 2 + e], qf[ks], kf4 + 2 * e);
      }
    }

    // Online softmax (rows r=lane/4 and r+8; quad reduce over lanes xor1,xor2)
    // (Q pre-scaled by SCALE in the QKV epilogue)
#pragma unroll
    for (int half = 0; half < 2; half++) {
      float mx = -1e30f;
#pragma unroll
      for (int nt = 0; nt < 8; nt++)
        mx = fmaxf(mx, fmaxf(s[nt][half * 2], s[nt][half * 2 + 1]));
      mx = fmaxf(mx, __shfl_xor_sync(0xffffffffu, mx, 1));
      mx = fmaxf(mx, __shfl_xor_sync(0xffffffffu, mx, 2));
      float mn = fmaxf(m_s[half], mx);
      float alpha = __expf(m_s[half] - mn);
      float ps = 0.f;
#pragma unroll
      for (int nt = 0; nt < 8; nt++) {
        float p0 = __expf(s[nt][half * 2] - mn);
        float p1 = __expf(s[nt][half * 2 + 1] - mn);
        s[nt][half * 2] = p0;
        s[nt][half * 2 + 1] = p1;
        ps += p0 + p1;
      }
      ps += __shfl_xor_sync(0xffffffffu, ps, 1);
      ps += __shfl_xor_sync(0xffffffffu, ps, 2);
      l_s[half] = l_s[half] * alpha + ps;
      m_s[half] = mn;
#pragma unroll
      for (int nt = 0; nt < 8; nt++) {
        o[nt][half * 2]     *= alpha;
        o[nt][half * 2 + 1] *= alpha;
      }
    }

    // O += P V (P packed fp16 in regs, V via ldmatrix.x4.trans)
#pragma unroll
    for (int ks = 0; ks < 4; ks++) {
      const int t0 = 2 * ks, t1 = 2 * ks + 1;
      uint32_t pa[4];
      pa[0] = pack_half2(s[t0][0], s[t0][1]);
      pa[1] = pack_half2(s[t0][2], s[t0][3]);
      pa[2] = pack_half2(s[t1][0], s[t1][1]);
      pa[3] = pack_half2(s[t1][2], s[t1][3]);
      int row = ks * 16 + (lane & 7) + ((lane >> 3) & 1) * 8;
#pragma unroll
      for (int ntp = 0; ntp < 4; ntp++) {
        uint32_t vf4[4];
        ldsm_x4_t(vf4, st + AKV + row * AROW +
                           (ntp * 2 + ((lane >> 4) & 1)) * 16);
#pragma unroll
        for (int e = 0; e < 2; e++)
          mma16816(o[ntp * 2 + e], pa, vf4 + 2 * e);
      }
    }
  }

  // Epilogue: normalize, write fp16 [B,L,D]
  const int b = bh >> 4, h = bh & 15;
#pragma unroll
  for (int half = 0; half < 2; half++) {
    const int row = q0 + wid * 16 + (lane >> 2) + half * 8;
    const float inv = 1.0f / l_s[half];
    const size_t base = ((size_t)(b * 2048 + row)) * 1024 + h * 64;
#pragma unroll
    for (int nt = 0; nt < 8; nt++) {
      const int d = nt * 8 + (lane & 3) * 2;
      *(uint32_t*)(g_a16 + base + d) =
          pack_half2(o[nt][half * 2] * inv, o[nt][half * 2 + 1] * inv);
    }
  }
}

// ---------------------------------------------------------------------------
extern "C" void kernel_launch(void* const* d_in, const int* in_sizes, int n_in,
                              void* d_out, int out_size) {
  const float* x      = (const float*)d_in[0];
  const float* qkv_w  = (const float*)d_in[1];
  const float* qkv_b  = (const float*)d_in[2];
  const float* proj_w = (const float*)d_in[3];
  const float* proj_b = (const float*)d_in[4];
  float* out = (float*)d_out;

  cudaFuncSetAttribute((const void*)hmma_gemm<0>,
                       cudaFuncAttributeMaxDynamicSharedMemorySize, GEMM_SMEM);
  cudaFuncSetAttribute((const void*)hmma_gemm<1>,
                       cudaFuncAttributeMaxDynamicSharedMemorySize, GEMM_SMEM);
  cudaFuncSetAttribute((const void*)attn_mma,
                       cudaFuncAttributeMaxDynamicSharedMemorySize, ATTN_SMEM);

  convert_all<<<(NALLQ + 255) / 256, 256>>>(x, qkv_w, proj_w);

  hmma_gemm<0><<<dim3(24, 64), 128, GEMM_SMEM>>>(qkv_b, nullptr);
  attn_mma<<<dim3(32, 32), 128, ATTN_SMEM>>>();
  hmma_gemm<1><<<dim3(8, 64), 128, GEMM_SMEM>>>(proj_b, out);
}